// round 6
// baseline (speedup 1.0000x reference)
#include <cuda_runtime.h>
#include <cuda_fp16.h>
#include <math.h>
#include <stdint.h>

#define TT 128
#define BB 256
#define DD 512
#define HH 1024
#define GG 4096   // 4*H

// ===================== scratch (static device globals) ======================
__device__ __align__(16) __half g_inc [(size_t)16 * 32768 * 64]; // inputs hi+lo (C=8)
__device__ __align__(16) __half g_xc  [(size_t)32 * 32768 * 64]; // x hi+lo      (C=16)
__device__ __align__(16) __half g_w1c [(size_t)8  * 1024  * 64]; // W1 hi only
__device__ __align__(16) __half g_wihc[(size_t)16 * 4096  * 64]; // W_ih hi only (gate-perm)
__device__ __align__(16) __half g_whhc[(size_t)32 * 4096  * 64]; // W_hh hi+lo   (gate-perm)
#define HSPLIT ((size_t)32 * 256 * 64)
__device__ __align__(16) __half g_hc  [2 * HSPLIT];              // h hi+lo, ping-pong
__device__ __align__(16) float g_xg[(size_t)TT * BB * GG];       // gate-perm cols
__device__ __align__(16) float g_c[BB * HH];
__device__ __align__(16) float g_bias[GG];                       // gate-perm

// ===================== PTX helpers ==========================================
__device__ __forceinline__ uint32_t smem_u32(const void* p) {
    return (uint32_t)__cvta_generic_to_shared(p);
}
__device__ __forceinline__ void cp_async16(uint32_t dst, const void* src) {
    asm volatile("cp.async.cg.shared.global [%0], [%1], 16;" :: "r"(dst), "l"(src));
}
__device__ __forceinline__ void cp_commit() {
    asm volatile("cp.async.commit_group;" ::: "memory");
}
template<int N>
__device__ __forceinline__ void cp_wait() {
    asm volatile("cp.async.wait_group %0;" :: "n"(N) : "memory");
}
__device__ __forceinline__ void ldsm_x4(uint32_t& r0, uint32_t& r1, uint32_t& r2, uint32_t& r3,
                                        uint32_t addr) {
    asm volatile("ldmatrix.sync.aligned.m8n8.x4.shared.b16 {%0,%1,%2,%3}, [%4];"
                 : "=r"(r0), "=r"(r1), "=r"(r2), "=r"(r3) : "r"(addr));
}
__device__ __forceinline__ void mma16816(float* c, const uint32_t* a, const uint32_t* b) {
    asm volatile(
        "mma.sync.aligned.m16n8k16.row.col.f32.f16.f16.f32 "
        "{%0,%1,%2,%3}, {%4,%5,%6,%7}, {%8,%9}, {%0,%1,%2,%3};"
        : "+f"(c[0]), "+f"(c[1]), "+f"(c[2]), "+f"(c[3])
        : "r"(a[0]), "r"(a[1]), "r"(a[2]), "r"(a[3]), "r"(b[0]), "r"(b[1]));
}

__device__ __forceinline__ void split2(float v, __half& hi, __half& lo) {
    hi = __float2half_rn(v);
    lo = __float2half_rn(v - __half2float(hi));
}

__device__ __forceinline__ void store_split(__half* dst, int M, int Cout,
                                            int m, int n, float v) {
    __half hi, lo; split2(v, hi, lo);
    const int chunk = n >> 6, col = n & 63;
    dst[((size_t)chunk * M + m) * 64 + col] = hi;
    dst[((size_t)(Cout + chunk) * M + m) * 64 + col] = lo;
}

// chunk loader: A tile RA rows, B tile RB rows, 128B rows, XOR-swizzled
#define LOAD_CHUNK(A_, B_, M_, N_, mB_, nB_, RA_, RB_, ac_, bc_, dA_)             \
    do {                                                                          \
        const char* As_ = (const char*)((A_) + ((size_t)(ac_) * (M_) + (mB_)) * 64);\
        const char* Bs_ = (const char*)((B_) + ((size_t)(bc_) * (N_) + (nB_)) * 64);\
        const uint32_t dB_ = (dA_) + (RA_) * 128u;                                \
        _Pragma("unroll")                                                         \
        for (int q_ = 0; q_ < (RA_) / 32; q_++) {                                 \
            const int e_ = tid + q_ * 256;                                        \
            const int r_ = e_ >> 3, s_ = e_ & 7;                                  \
            const uint32_t off_ = r_ * 128 + (((uint32_t)(s_ ^ (r_ & 7))) << 4);  \
            cp_async16((dA_) + off_, As_ + r_ * 128 + s_ * 16);                   \
        }                                                                         \
        _Pragma("unroll")                                                         \
        for (int q_ = 0; q_ < (RB_) / 32; q_++) {                                 \
            const int e_ = tid + q_ * 256;                                        \
            const int r_ = e_ >> 3, s_ = e_ & 7;                                  \
            const uint32_t off_ = r_ * 128 + (((uint32_t)(s_ ^ (r_ & 7))) << 4);  \
            cp_async16(dB_ + off_, Bs_ + r_ * 128 + s_ * 16);                     \
        }                                                                         \
    } while (0)

// 2-pass map: (A hi, B hi), (A lo, B hi)
__device__ __forceinline__ void chunk_map2(int i, int C, int& ac, int& bc) {
    const int p = i / C, ci = i - p * C;
    ac = (p == 1) ? C + ci : ci;
    bc = ci;
}

// ===================== big GEMMs (BM=BN=128, 3-stage, 2 CTA/SM) ==============
// MODE 0: v=relu(v+aux[n]) -> split store; MODE 1: v=v+aux[n] -> outF
template<int MODE>
__global__ __launch_bounds__(256, 2)
void gemm_mma(const __half* __restrict__ A, const __half* __restrict__ B,
              const float* __restrict__ aux, float* __restrict__ outF,
              __half* __restrict__ outSplit, int M, int N, int C)
{
    extern __shared__ char smraw[];
    const uint32_t sbase = smem_u32(smraw);   // 3 stages x (A 16KB | B 16KB)

    const int tid  = threadIdx.x;
    const int lane = tid & 31;
    const int wid  = tid >> 5;
    const int wm   = wid & 3;
    const int wn   = wid >> 2;
    const int mBase = blockIdx.y * 128;
    const int nBase = blockIdx.x * 128;
    const int NIT = 2 * C;

    float c[2][8][4];
#pragma unroll
    for (int i = 0; i < 2; i++)
#pragma unroll
        for (int j = 0; j < 8; j++)
#pragma unroll
            for (int k = 0; k < 4; k++) c[i][j][k] = 0.0f;

    const int lrow_a = ((lane >> 3) & 1) * 8 + (lane & 7);
    const int lrow_b = (lane >> 4) * 8 + (lane & 7);
    const int lxor   = lane & 7;
    const int ahalf  = lane >> 4;
    const int bhalf  = (lane >> 3) & 1;

    uint32_t stg[3] = { sbase, sbase + 32768u, sbase + 65536u };

    // prefetch stages 0,1
#pragma unroll
    for (int p = 0; p < 2; p++) {
        int ac, bc; chunk_map2(p, C, ac, bc);
        LOAD_CHUNK(A, B, M, N, mBase, nBase, 128, 128, ac, bc, stg[p]);
        cp_commit();
    }

    for (int i = 0; i < NIT; i++) {
        if (i == NIT - 1) cp_wait<0>(); else cp_wait<1>();
        __syncthreads();
        if (i + 2 < NIT) {
            int ac, bc; chunk_map2(i + 2, C, ac, bc);
            LOAD_CHUNK(A, B, M, N, mBase, nBase, 128, 128, ac, bc, stg[(i + 2) % 3]);
            cp_commit();
        }

        const uint32_t aTile = stg[i % 3];
        const uint32_t bTile = aTile + 16384u;
#pragma unroll
        for (int kk = 0; kk < 4; kk++) {
            uint32_t a[2][4], b[8][2];
#pragma unroll
            for (int mt = 0; mt < 2; mt++) {
                const int row = wm * 32 + mt * 16 + lrow_a;
                const uint32_t addr = aTile + row * 128 +
                    (((uint32_t)((kk * 2 + ahalf) ^ lxor)) << 4);
                ldsm_x4(a[mt][0], a[mt][1], a[mt][2], a[mt][3], addr);
            }
#pragma unroll
            for (int bt = 0; bt < 4; bt++) {
                const int row = wn * 64 + bt * 16 + lrow_b;
                const uint32_t addr = bTile + row * 128 +
                    (((uint32_t)((kk * 2 + bhalf) ^ lxor)) << 4);
                uint32_t r0, r1, r2, r3;
                ldsm_x4(r0, r1, r2, r3, addr);
                b[2 * bt][0] = r0;     b[2 * bt][1] = r1;
                b[2 * bt + 1][0] = r2; b[2 * bt + 1][1] = r3;
            }
#pragma unroll
            for (int mt = 0; mt < 2; mt++)
#pragma unroll
                for (int nt = 0; nt < 8; nt++)
                    mma16816(c[mt][nt], a[mt], b[nt]);
        }
    }

    const int g  = lane >> 2;
    const int tg = lane & 3;
    const int Cout = N >> 6;
#pragma unroll
    for (int mt = 0; mt < 2; mt++) {
        const int m0 = mBase + wm * 32 + mt * 16 + g;
#pragma unroll
        for (int nt = 0; nt < 8; nt++) {
            const int n0 = nBase + wn * 64 + nt * 8 + tg * 2;
#pragma unroll
            for (int half = 0; half < 2; half++) {
                const int m = m0 + half * 8;
                const float v0 = c[mt][nt][half * 2 + 0];
                const float v1 = c[mt][nt][half * 2 + 1];
                if (MODE == 0) {
                    store_split(outSplit, M, Cout, m, n0,     fmaxf(v0 + aux[n0],     0.0f));
                    store_split(outSplit, M, Cout, m, n0 + 1, fmaxf(v1 + aux[n0 + 1], 0.0f));
                } else {
                    float2 r = make_float2(v0 + aux[n0], v1 + aux[n0 + 1]);
                    *(float2*)(outF + (size_t)m * N + n0) = r;
                }
            }
        }
    }
}

// ===================== fused recurrence step (3-pass fp16, 3-stage) ==========
#define GATE_W 68
__device__ __forceinline__ float sigf(float x) { return 1.0f / (1.0f + __expf(-x)); }

__global__ __launch_bounds__(256)
void rec_step_k(const __half* __restrict__ hcR, __half* __restrict__ hcW,
                const __half* __restrict__ whh, const float* __restrict__ xg,
                const float* __restrict__ W_out,
                float* __restrict__ out, float* __restrict__ hT, float* __restrict__ cT,
                int t)
{
    extern __shared__ char smraw[];
    const uint32_t sbase = smem_u32(smraw);   // 3 stages x (A 16KB | B 8KB) = 72KB
    float* gate_sm = (float*)smraw;           // aliases stages post-mainloop

    const int tid  = threadIdx.x;
    const int lane = tid & 31;
    const int wid  = tid >> 5;
    const int wm   = wid & 3;
    const int wn   = wid >> 2;
    const int nBase = blockIdx.x * 64;
    const int mBase = blockIdx.y * 128;
    const int C = 16, NIT = 48;

    float c[2][4][4];
#pragma unroll
    for (int i = 0; i < 2; i++)
#pragma unroll
        for (int j = 0; j < 4; j++)
#pragma unroll
            for (int k = 0; k < 4; k++) c[i][j][k] = 0.0f;

    const int lrow_a = ((lane >> 3) & 1) * 8 + (lane & 7);
    const int lrow_b = (lane >> 4) * 8 + (lane & 7);
    const int lxor   = lane & 7;
    const int ahalf  = lane >> 4;
    const int bhalf  = (lane >> 3) & 1;

    // 3-pass map: p0 (Ahi,Bhi)  p1 (Ahi,Blo)  p2 (Alo,Bhi)
#define MAP3(i_, ac_, bc_)                              \
    {   const int p_ = (i_) / C, ci_ = (i_) - p_ * C;   \
        ac_ = (p_ == 2) ? C + ci_ : ci_;                \
        bc_ = (p_ == 1) ? C + ci_ : ci_; }

    uint32_t stg[3] = { sbase, sbase + 24576u, sbase + 49152u };

#pragma unroll
    for (int p = 0; p < 2; p++) {
        int ac, bc; MAP3(p, ac, bc);
        LOAD_CHUNK(hcR, whh, 256, 4096, mBase, nBase, 128, 64, ac, bc, stg[p]);
        cp_commit();
    }

    for (int i = 0; i < NIT; i++) {
        if (i == NIT - 1) cp_wait<0>(); else cp_wait<1>();
        __syncthreads();
        if (i + 2 < NIT) {
            int ac, bc; MAP3(i + 2, ac, bc);
            LOAD_CHUNK(hcR, whh, 256, 4096, mBase, nBase, 128, 64, ac, bc, stg[(i + 2) % 3]);
            cp_commit();
        }

        const uint32_t aTile = stg[i % 3];
        const uint32_t bTile = aTile + 16384u;
#pragma unroll
        for (int kk = 0; kk < 4; kk++) {
            uint32_t a[2][4], b[4][2];
#pragma unroll
            for (int mt = 0; mt < 2; mt++) {
                const int row = wm * 32 + mt * 16 + lrow_a;
                const uint32_t addr = aTile + row * 128 +
                    (((uint32_t)((kk * 2 + ahalf) ^ lxor)) << 4);
                ldsm_x4(a[mt][0], a[mt][1], a[mt][2], a[mt][3], addr);
            }
#pragma unroll
            for (int bt = 0; bt < 2; bt++) {
                const int row = wn * 32 + bt * 16 + lrow_b;
                const uint32_t addr = bTile + row * 128 +
                    (((uint32_t)((kk * 2 + bhalf) ^ lxor)) << 4);
                uint32_t r0, r1, r2, r3;
                ldsm_x4(r0, r1, r2, r3, addr);
                b[2 * bt][0] = r0;     b[2 * bt][1] = r1;
                b[2 * bt + 1][0] = r2; b[2 * bt + 1][1] = r3;
            }
#pragma unroll
            for (int mt = 0; mt < 2; mt++)
#pragma unroll
                for (int nt = 0; nt < 4; nt++)
                    mma16816(c[mt][nt], a[mt], b[nt]);
        }
    }
#undef MAP3

    __syncthreads();   // stage buffers retire before gate_sm alias writes

    const int g  = lane >> 2;
    const int tg = lane & 3;
#pragma unroll
    for (int mt = 0; mt < 2; mt++) {
#pragma unroll
        for (int nt = 0; nt < 4; nt++) {
            const int col = wn * 32 + nt * 8 + tg * 2;
#pragma unroll
            for (int half = 0; half < 2; half++) {
                const int row = wm * 32 + mt * 16 + g + half * 8;
                const float* xp = xg + (size_t)(mBase + row) * GG + nBase + col;
                gate_sm[row * GATE_W + col]     = c[mt][nt][half * 2 + 0] + xp[0];
                gate_sm[row * GATE_W + col + 1] = c[mt][nt][half * 2 + 1] + xp[1];
            }
        }
    }
    __syncthreads();

    const int bloc = tid >> 1;
    const int b = mBase + bloc;
    const int jh = (tid & 1) * 8;
    float osum = 0.0f;
#pragma unroll
    for (int jj = 0; jj < 8; jj++) {
        const int jloc = jh + jj;
        const int j = (nBase >> 2) + jloc;
        const float4 gt = *(const float4*)&gate_sm[bloc * GATE_W + jloc * 4];
        const float ig = sigf(gt.x);
        const float fg = sigf(gt.y);
        const float gg = tanhf(gt.z);
        const float og = sigf(gt.w);
        const float cc = fg * g_c[b * HH + j] + ig * gg;
        const float h  = og * tanhf(cc);
        g_c[b * HH + j] = cc;

        __half hi, lo; split2(h, hi, lo);
        const int chunk = j >> 6, col = j & 63;
        hcW[((size_t)chunk * BB + b) * 64 + col] = hi;
        hcW[((size_t)(16 + chunk) * BB + b) * 64 + col] = lo;

        osum += h * W_out[j];
        if (t == TT - 1) { hT[b * HH + j] = h; cT[b * HH + j] = cc; }
    }
    atomicAdd(&out[t * BB + b], osum);
}

// ===================== conversion / pointwise kernels ========================
__global__ void split_k(const float* __restrict__ src, __half* __restrict__ dst,
                        int R, int K)
{
    const size_t i = (size_t)blockIdx.x * blockDim.x + threadIdx.x;
    const int r = (int)(i / K);
    const int k = (int)(i - (size_t)r * K);
    __half hi, lo; split2(src[i], hi, lo);
    const int C = K >> 6;
    const int chunk = k >> 6, col = k & 63;
    dst[((size_t)chunk * R + r) * 64 + col] = hi;
    dst[((size_t)(C + chunk) * R + r) * 64 + col] = lo;
}

__global__ void split_hi_k(const float* __restrict__ src, __half* __restrict__ dst,
                           int R, int K)
{
    const size_t i = (size_t)blockIdx.x * blockDim.x + threadIdx.x;
    const int r = (int)(i / K);
    const int k = (int)(i - (size_t)r * K);
    const int chunk = k >> 6, col = k & 63;
    dst[((size_t)chunk * R + r) * 64 + col] = __float2half_rn(src[i]);
}

__global__ void split_perm_hi_k(const float* __restrict__ src, __half* __restrict__ dst)
{
    const size_t i = (size_t)blockIdx.x * blockDim.x + threadIdx.x;
    const int r = (int)(i >> 10);
    const int k = (int)(i & 1023);
    const int gt = r >> 10, j = r & 1023;
    const int rp = j * 4 + gt;
    const int chunk = k >> 6, col = k & 63;
    dst[((size_t)chunk * 4096 + rp) * 64 + col] = __float2half_rn(src[i]);
}

__global__ void split_perm_k(const float* __restrict__ src, __half* __restrict__ dst)
{
    const size_t i = (size_t)blockIdx.x * blockDim.x + threadIdx.x;
    const int r = (int)(i >> 10);
    const int k = (int)(i & 1023);
    const int gt = r >> 10, j = r & 1023;
    const int rp = j * 4 + gt;
    __half hi, lo; split2(src[i], hi, lo);
    const int chunk = k >> 6, col = k & 63;
    dst[((size_t)chunk * 4096 + rp) * 64 + col] = hi;
    dst[((size_t)(16 + chunk) * 4096 + rp) * 64 + col] = lo;
}

__global__ void combine_bias_k(const float* __restrict__ b_ih, const float* __restrict__ b_hh)
{
    int i = blockIdx.x * blockDim.x + threadIdx.x;
    if (i < GG) {
        const int gt = i & 3, j = i >> 2;
        const int s = gt * HH + j;
        g_bias[i] = b_ih[s] + b_hh[s];
    }
}

__global__ void init_state_k(const float* __restrict__ h0, const float* __restrict__ c0)
{
    const int i = blockIdx.x * blockDim.x + threadIdx.x;
    const int b = i >> 10, j = i & 1023;
    g_c[i] = c0[i];
    __half hi, lo; split2(h0[i], hi, lo);
    const int chunk = j >> 6, col = j & 63;
    g_hc[((size_t)chunk * BB + b) * 64 + col] = hi;
    g_hc[((size_t)(16 + chunk) * BB + b) * 64 + col] = lo;
}

__global__ void out_init_k(float* __restrict__ out, const float* __restrict__ b_out)
{
    const int i = blockIdx.x * blockDim.x + threadIdx.x;
    if (i < TT * BB) out[i] = b_out[0];
}

// ===================== launch ================================================
#define SMEM_BIG 98304
#define SMEM_REC 73728

extern "C" void kernel_launch(void* const* d_in, const int* in_sizes, int n_in,
                              void* d_out, int out_size)
{
    const float* inputs = (const float*)d_in[0];
    const float* h0     = (const float*)d_in[1];
    const float* c0     = (const float*)d_in[2];
    const float* W1     = (const float*)d_in[3];
    const float* b1     = (const float*)d_in[4];
    const float* W_ih   = (const float*)d_in[5];
    const float* W_hh   = (const float*)d_in[6];
    const float* b_ih   = (const float*)d_in[7];
    const float* b_hh   = (const float*)d_in[8];
    const float* W_out  = (const float*)d_in[9];
    const float* b_out  = (const float*)d_in[10];

    float* out = (float*)d_out;
    float* hT  = out + TT * BB;
    float* cT  = hT + BB * HH;

    __half *pinc, *pxc, *pw1c, *pwihc, *pwhhc, *phc;
    float *pxg, *pbias;
    cudaGetSymbolAddress((void**)&pinc,  g_inc);
    cudaGetSymbolAddress((void**)&pxc,   g_xc);
    cudaGetSymbolAddress((void**)&pw1c,  g_w1c);
    cudaGetSymbolAddress((void**)&pwihc, g_wihc);
    cudaGetSymbolAddress((void**)&pwhhc, g_whhc);
    cudaGetSymbolAddress((void**)&phc,   g_hc);
    cudaGetSymbolAddress((void**)&pxg,   g_xg);
    cudaGetSymbolAddress((void**)&pbias, g_bias);

    cudaFuncSetAttribute(gemm_mma<0>, cudaFuncAttributeMaxDynamicSharedMemorySize, SMEM_BIG);
    cudaFuncSetAttribute(gemm_mma<1>, cudaFuncAttributeMaxDynamicSharedMemorySize, SMEM_BIG);
    cudaFuncSetAttribute(rec_step_k,  cudaFuncAttributeMaxDynamicSharedMemorySize, SMEM_REC);

    // launches ordered so gemm_mma<1> (GEMM2) is launch #6 for ncu -s 5 -c 1
    split_k<<<(32768 * 512) / 256, 256>>>(inputs, pinc, 32768, 512);          // 1
    split_hi_k<<<(1024 * 512) / 256, 256>>>(W1, pw1c, 1024, 512);             // 2
    combine_bias_k<<<GG / 256, 256>>>(b_ih, b_hh);                            // 3
    split_perm_hi_k<<<(4096 * 1024) / 256, 256>>>(W_ih, pwihc);               // 4
    {
        dim3 grid(HH / 128, 32768 / 128);                                     // 5: GEMM1
        gemm_mma<0><<<grid, 256, SMEM_BIG>>>(pinc, pw1c, b1, nullptr, pxc, 32768, HH, 8);
    }
    {
        dim3 grid(GG / 128, 32768 / 128);                                     // 6: GEMM2
        gemm_mma<1><<<grid, 256, SMEM_BIG>>>(pxc, pwihc, pbias, pxg, nullptr, 32768, GG, 16);
    }
    split_perm_k<<<(4096 * 1024) / 256, 256>>>(W_hh, pwhhc);                  // 7
    init_state_k<<<(BB * HH) / 256, 256>>>(h0, c0);                           // 8
    out_init_k<<<(TT * BB) / 256, 256>>>(out, b_out);                         // 9

    {
        dim3 grid(GG / 64, BB / 128);   // 128 CTAs
        for (int t = 0; t < TT; t++) {
            rec_step_k<<<grid, 256, SMEM_REC>>>(
                phc + (t & 1) * HSPLIT, phc + ((t + 1) & 1) * HSPLIT,
                pwhhc, pxg + (size_t)t * BB * GG, W_out, out, hT, cT, t);
        }
    }
}

// round 7
// speedup vs baseline: 1.3897x; 1.3897x over previous
#include <cuda_runtime.h>
#include <cuda_fp16.h>
#include <math.h>
#include <stdint.h>

#define TT 128
#define BB 256
#define DD 512
#define HH 1024
#define GG 4096   // 4*H

// ===================== scratch (static device globals) ======================
__device__ __align__(16) __half g_inc [(size_t)16 * 32768 * 64]; // inputs hi+lo (C=8)
__device__ __align__(16) __half g_xc  [(size_t)32 * 32768 * 64]; // x hi+lo      (C=16)
__device__ __align__(16) __half g_w1c [(size_t)8  * 1024  * 64]; // W1 hi only
__device__ __align__(16) __half g_wihc[(size_t)16 * 4096  * 64]; // W_ih hi only (gate-perm)
__device__ __align__(16) __half g_whhc[(size_t)16 * 4096  * 64]; // W_hh hi only (gate-perm)
#define HSPLIT ((size_t)32 * 256 * 64)
__device__ __align__(16) __half g_hc  [2 * HSPLIT];              // h hi+lo, ping-pong
__device__ __align__(16) float g_xg[(size_t)TT * BB * GG];       // gate-perm cols
__device__ __align__(16) float g_c[BB * HH];
__device__ __align__(16) float g_bias[GG];                       // gate-perm

// ===================== PTX helpers ==========================================
__device__ __forceinline__ uint32_t smem_u32(const void* p) {
    return (uint32_t)__cvta_generic_to_shared(p);
}
__device__ __forceinline__ void cp_async16(uint32_t dst, const void* src) {
    asm volatile("cp.async.cg.shared.global [%0], [%1], 16;" :: "r"(dst), "l"(src));
}
__device__ __forceinline__ void cp_commit() {
    asm volatile("cp.async.commit_group;" ::: "memory");
}
template<int N>
__device__ __forceinline__ void cp_wait() {
    asm volatile("cp.async.wait_group %0;" :: "n"(N) : "memory");
}
__device__ __forceinline__ void ldsm_x4(uint32_t& r0, uint32_t& r1, uint32_t& r2, uint32_t& r3,
                                        uint32_t addr) {
    asm volatile("ldmatrix.sync.aligned.m8n8.x4.shared.b16 {%0,%1,%2,%3}, [%4];"
                 : "=r"(r0), "=r"(r1), "=r"(r2), "=r"(r3) : "r"(addr));
}
__device__ __forceinline__ void mma16816(float* c, const uint32_t* a, const uint32_t* b) {
    asm volatile(
        "mma.sync.aligned.m16n8k16.row.col.f32.f16.f16.f32 "
        "{%0,%1,%2,%3}, {%4,%5,%6,%7}, {%8,%9}, {%0,%1,%2,%3};"
        : "+f"(c[0]), "+f"(c[1]), "+f"(c[2]), "+f"(c[3])
        : "r"(a[0]), "r"(a[1]), "r"(a[2]), "r"(a[3]), "r"(b[0]), "r"(b[1]));
}

__device__ __forceinline__ void split2(float v, __half& hi, __half& lo) {
    hi = __float2half_rn(v);
    lo = __float2half_rn(v - __half2float(hi));
}

__device__ __forceinline__ void store_split(__half* dst, int M, int Cout,
                                            int m, int n, float v) {
    __half hi, lo; split2(v, hi, lo);
    const int chunk = n >> 6, col = n & 63;
    dst[((size_t)chunk * M + m) * 64 + col] = hi;
    dst[((size_t)(Cout + chunk) * M + m) * 64 + col] = lo;
}

// chunk loader: A tile RA rows, B tile RB rows, 128B rows, XOR-swizzled
#define LOAD_CHUNK(A_, B_, M_, N_, mB_, nB_, RA_, RB_, ac_, bc_, dA_)             \
    do {                                                                          \
        const char* As_ = (const char*)((A_) + ((size_t)(ac_) * (M_) + (mB_)) * 64);\
        const char* Bs_ = (const char*)((B_) + ((size_t)(bc_) * (N_) + (nB_)) * 64);\
        const uint32_t dB_ = (dA_) + (RA_) * 128u;                                \
        _Pragma("unroll")                                                         \
        for (int q_ = 0; q_ < (RA_) / 32; q_++) {                                 \
            const int e_ = tid + q_ * 256;                                        \
            const int r_ = e_ >> 3, s_ = e_ & 7;                                  \
            const uint32_t off_ = r_ * 128 + (((uint32_t)(s_ ^ (r_ & 7))) << 4);  \
            cp_async16((dA_) + off_, As_ + r_ * 128 + s_ * 16);                   \
        }                                                                         \
        _Pragma("unroll")                                                         \
        for (int q_ = 0; q_ < (RB_) / 32; q_++) {                                 \
            const int e_ = tid + q_ * 256;                                        \
            const int r_ = e_ >> 3, s_ = e_ & 7;                                  \
            const uint32_t off_ = r_ * 128 + (((uint32_t)(s_ ^ (r_ & 7))) << 4);  \
            cp_async16(dB_ + off_, Bs_ + r_ * 128 + s_ * 16);                     \
        }                                                                         \
    } while (0)

// 2-pass map: (A hi, B hi), (A lo, B hi)
__device__ __forceinline__ void chunk_map2(int i, int C, int& ac, int& bc) {
    const int p = i / C, ci = i - p * C;
    ac = (p == 1) ? C + ci : ci;
    bc = ci;
}

// ===================== big GEMMs (BM=BN=128, 2-pass fp16, 2 CTA/SM) ==========
// MODE 0: v=relu(v+aux[n]) -> split store; MODE 1: v=v+aux[n] -> outF
template<int MODE>
__global__ __launch_bounds__(256, 2)
void gemm_mma(const __half* __restrict__ A, const __half* __restrict__ B,
              const float* __restrict__ aux, float* __restrict__ outF,
              __half* __restrict__ outSplit, int M, int N, int C)
{
    extern __shared__ char smraw[];
    const uint32_t sbase = smem_u32(smraw);   // [2 bufs][A 16KB | B 16KB]

    const int tid  = threadIdx.x;
    const int lane = tid & 31;
    const int wid  = tid >> 5;
    const int wm   = wid & 3;
    const int wn   = wid >> 2;
    const int mBase = blockIdx.y * 128;
    const int nBase = blockIdx.x * 128;
    const int NIT = 2 * C;

    float c[2][8][4];
#pragma unroll
    for (int i = 0; i < 2; i++)
#pragma unroll
        for (int j = 0; j < 8; j++)
#pragma unroll
            for (int k = 0; k < 4; k++) c[i][j][k] = 0.0f;

    const int lrow_a = ((lane >> 3) & 1) * 8 + (lane & 7);
    const int lrow_b = (lane >> 4) * 8 + (lane & 7);
    const int lxor   = lane & 7;
    const int ahalf  = lane >> 4;
    const int bhalf  = (lane >> 3) & 1;

    {
        int ac, bc; chunk_map2(0, C, ac, bc);
        LOAD_CHUNK(A, B, M, N, mBase, nBase, 128, 128, ac, bc, sbase);
        cp_commit();
    }

    for (int i = 0; i < NIT; i++) {
        const int buf = i & 1;
        if (i + 1 < NIT) {
            int ac, bc; chunk_map2(i + 1, C, ac, bc);
            LOAD_CHUNK(A, B, M, N, mBase, nBase, 128, 128, ac, bc,
                       sbase + ((i + 1) & 1) * 32768u);
            cp_commit();
            cp_wait<1>();
        } else {
            cp_wait<0>();
        }
        __syncthreads();

        const uint32_t aTile = sbase + buf * 32768u;
        const uint32_t bTile = aTile + 16384u;
#pragma unroll
        for (int kk = 0; kk < 4; kk++) {
            uint32_t a[2][4], b[8][2];
#pragma unroll
            for (int mt = 0; mt < 2; mt++) {
                const int row = wm * 32 + mt * 16 + lrow_a;
                const uint32_t addr = aTile + row * 128 +
                    (((uint32_t)((kk * 2 + ahalf) ^ lxor)) << 4);
                ldsm_x4(a[mt][0], a[mt][1], a[mt][2], a[mt][3], addr);
            }
#pragma unroll
            for (int bt = 0; bt < 4; bt++) {
                const int row = wn * 64 + bt * 16 + lrow_b;
                const uint32_t addr = bTile + row * 128 +
                    (((uint32_t)((kk * 2 + bhalf) ^ lxor)) << 4);
                uint32_t r0, r1, r2, r3;
                ldsm_x4(r0, r1, r2, r3, addr);
                b[2 * bt][0] = r0;     b[2 * bt][1] = r1;
                b[2 * bt + 1][0] = r2; b[2 * bt + 1][1] = r3;
            }
#pragma unroll
            for (int mt = 0; mt < 2; mt++)
#pragma unroll
                for (int nt = 0; nt < 8; nt++)
                    mma16816(c[mt][nt], a[mt], b[nt]);
        }
        __syncthreads();
    }

    const int g  = lane >> 2;
    const int tg = lane & 3;
    const int Cout = N >> 6;
#pragma unroll
    for (int mt = 0; mt < 2; mt++) {
        const int m0 = mBase + wm * 32 + mt * 16 + g;
#pragma unroll
        for (int nt = 0; nt < 8; nt++) {
            const int n0 = nBase + wn * 64 + nt * 8 + tg * 2;
#pragma unroll
            for (int half = 0; half < 2; half++) {
                const int m = m0 + half * 8;
                const float v0 = c[mt][nt][half * 2 + 0];
                const float v1 = c[mt][nt][half * 2 + 1];
                if (MODE == 0) {
                    store_split(outSplit, M, Cout, m, n0,     fmaxf(v0 + aux[n0],     0.0f));
                    store_split(outSplit, M, Cout, m, n0 + 1, fmaxf(v1 + aux[n0 + 1], 0.0f));
                } else {
                    float2 r = make_float2(v0 + aux[n0], v1 + aux[n0 + 1]);
                    *(float2*)(outF + (size_t)m * N + n0) = r;
                }
            }
        }
    }
}

// ===================== fused recurrence step (2-pass fp16) ===================
// gates = h_exact @ fp16(Whh)'^T + xg'(t): passes (Ahi,Bhi),(Alo,Bhi)
#define GATE_W 68
__device__ __forceinline__ float sigf(float x) { return 1.0f / (1.0f + __expf(-x)); }

__global__ __launch_bounds__(256)
void rec_step_k(const __half* __restrict__ hcR, __half* __restrict__ hcW,
                const __half* __restrict__ whh, const float* __restrict__ xg,
                const float* __restrict__ W_out,
                float* __restrict__ out, float* __restrict__ hT, float* __restrict__ cT,
                int t)
{
    extern __shared__ char smraw[];
    const uint32_t sbase = smem_u32(smraw);   // [2 bufs][A 16KB | B 8KB] = 48KB
    float* gate_sm = (float*)smraw;

    const int tid  = threadIdx.x;
    const int lane = tid & 31;
    const int wid  = tid >> 5;
    const int wm   = wid & 3;
    const int wn   = wid >> 2;
    const int nBase = blockIdx.x * 64;
    const int mBase = blockIdx.y * 128;
    const int C = 16, NIT = 32;

    float c[2][4][4];
#pragma unroll
    for (int i = 0; i < 2; i++)
#pragma unroll
        for (int j = 0; j < 4; j++)
#pragma unroll
            for (int k = 0; k < 4; k++) c[i][j][k] = 0.0f;

    const int lrow_a = ((lane >> 3) & 1) * 8 + (lane & 7);
    const int lrow_b = (lane >> 4) * 8 + (lane & 7);
    const int lxor   = lane & 7;
    const int ahalf  = lane >> 4;
    const int bhalf  = (lane >> 3) & 1;

    {
        int ac, bc; chunk_map2(0, C, ac, bc);
        LOAD_CHUNK(hcR, whh, 256, 4096, mBase, nBase, 128, 64, ac, bc, sbase);
        cp_commit();
    }

    for (int i = 0; i < NIT; i++) {
        const int buf = i & 1;
        if (i + 1 < NIT) {
            int ac, bc; chunk_map2(i + 1, C, ac, bc);
            LOAD_CHUNK(hcR, whh, 256, 4096, mBase, nBase, 128, 64, ac, bc,
                       sbase + ((i + 1) & 1) * 24576u);
            cp_commit();
            cp_wait<1>();
        } else {
            cp_wait<0>();
        }
        __syncthreads();

        const uint32_t aTile = sbase + buf * 24576u;
        const uint32_t bTile = aTile + 16384u;
#pragma unroll
        for (int kk = 0; kk < 4; kk++) {
            uint32_t a[2][4], b[4][2];
#pragma unroll
            for (int mt = 0; mt < 2; mt++) {
                const int row = wm * 32 + mt * 16 + lrow_a;
                const uint32_t addr = aTile + row * 128 +
                    (((uint32_t)((kk * 2 + ahalf) ^ lxor)) << 4);
                ldsm_x4(a[mt][0], a[mt][1], a[mt][2], a[mt][3], addr);
            }
#pragma unroll
            for (int bt = 0; bt < 2; bt++) {
                const int row = wn * 32 + bt * 16 + lrow_b;
                const uint32_t addr = bTile + row * 128 +
                    (((uint32_t)((kk * 2 + bhalf) ^ lxor)) << 4);
                uint32_t r0, r1, r2, r3;
                ldsm_x4(r0, r1, r2, r3, addr);
                b[2 * bt][0] = r0;     b[2 * bt][1] = r1;
                b[2 * bt + 1][0] = r2; b[2 * bt + 1][1] = r3;
            }
#pragma unroll
            for (int mt = 0; mt < 2; mt++)
#pragma unroll
                for (int nt = 0; nt < 4; nt++)
                    mma16816(c[mt][nt], a[mt], b[nt]);
        }
        __syncthreads();
    }

    const int g  = lane >> 2;
    const int tg = lane & 3;
#pragma unroll
    for (int mt = 0; mt < 2; mt++) {
#pragma unroll
        for (int nt = 0; nt < 4; nt++) {
            const int col = wn * 32 + nt * 8 + tg * 2;
#pragma unroll
            for (int half = 0; half < 2; half++) {
                const int row = wm * 32 + mt * 16 + g + half * 8;
                const float* xp = xg + (size_t)(mBase + row) * GG + nBase + col;
                gate_sm[row * GATE_W + col]     = c[mt][nt][half * 2 + 0] + xp[0];
                gate_sm[row * GATE_W + col + 1] = c[mt][nt][half * 2 + 1] + xp[1];
            }
        }
    }
    __syncthreads();

    const int bloc = tid >> 1;
    const int b = mBase + bloc;
    const int jh = (tid & 1) * 8;
    float osum = 0.0f;
#pragma unroll
    for (int jj = 0; jj < 8; jj++) {
        const int jloc = jh + jj;
        const int j = (nBase >> 2) + jloc;
        const float4 gt = *(const float4*)&gate_sm[bloc * GATE_W + jloc * 4];
        const float ig = sigf(gt.x);
        const float fg = sigf(gt.y);
        const float gg = tanhf(gt.z);
        const float og = sigf(gt.w);
        const float cc = fg * g_c[b * HH + j] + ig * gg;
        const float h  = og * tanhf(cc);
        g_c[b * HH + j] = cc;

        __half hi, lo; split2(h, hi, lo);
        const int chunk = j >> 6, col = j & 63;
        hcW[((size_t)chunk * BB + b) * 64 + col] = hi;
        hcW[((size_t)(16 + chunk) * BB + b) * 64 + col] = lo;

        osum += h * W_out[j];
        if (t == TT - 1) { hT[b * HH + j] = h; cT[b * HH + j] = cc; }
    }
    atomicAdd(&out[t * BB + b], osum);
}

// ===================== conversion / pointwise kernels ========================
__global__ void split_k(const float* __restrict__ src, __half* __restrict__ dst,
                        int R, int K)
{
    const size_t i = (size_t)blockIdx.x * blockDim.x + threadIdx.x;
    const int r = (int)(i / K);
    const int k = (int)(i - (size_t)r * K);
    __half hi, lo; split2(src[i], hi, lo);
    const int C = K >> 6;
    const int chunk = k >> 6, col = k & 63;
    dst[((size_t)chunk * R + r) * 64 + col] = hi;
    dst[((size_t)(C + chunk) * R + r) * 64 + col] = lo;
}

__global__ void split_hi_k(const float* __restrict__ src, __half* __restrict__ dst,
                           int R, int K)
{
    const size_t i = (size_t)blockIdx.x * blockDim.x + threadIdx.x;
    const int r = (int)(i / K);
    const int k = (int)(i - (size_t)r * K);
    const int chunk = k >> 6, col = k & 63;
    dst[((size_t)chunk * R + r) * 64 + col] = __float2half_rn(src[i]);
}

// gate-permuted, hi-only: dest row r' = j*4+g  (used for W_ih and W_hh)
__global__ void split_perm_hi_k(const float* __restrict__ src, __half* __restrict__ dst)
{
    const size_t i = (size_t)blockIdx.x * blockDim.x + threadIdx.x;
    const int r = (int)(i >> 10);
    const int k = (int)(i & 1023);
    const int gt = r >> 10, j = r & 1023;
    const int rp = j * 4 + gt;
    const int chunk = k >> 6, col = k & 63;
    dst[((size_t)chunk * 4096 + rp) * 64 + col] = __float2half_rn(src[i]);
}

__global__ void combine_bias_k(const float* __restrict__ b_ih, const float* __restrict__ b_hh)
{
    int i = blockIdx.x * blockDim.x + threadIdx.x;
    if (i < GG) {
        const int gt = i & 3, j = i >> 2;
        const int s = gt * HH + j;
        g_bias[i] = b_ih[s] + b_hh[s];
    }
}

__global__ void init_state_k(const float* __restrict__ h0, const float* __restrict__ c0)
{
    const int i = blockIdx.x * blockDim.x + threadIdx.x;
    const int b = i >> 10, j = i & 1023;
    g_c[i] = c0[i];
    __half hi, lo; split2(h0[i], hi, lo);
    const int chunk = j >> 6, col = j & 63;
    g_hc[((size_t)chunk * BB + b) * 64 + col] = hi;
    g_hc[((size_t)(16 + chunk) * BB + b) * 64 + col] = lo;
}

__global__ void out_init_k(float* __restrict__ out, const float* __restrict__ b_out)
{
    const int i = blockIdx.x * blockDim.x + threadIdx.x;
    if (i < TT * BB) out[i] = b_out[0];
}

// ===================== launch ================================================
#define SMEM_BIG 65536
#define SMEM_REC 49152

extern "C" void kernel_launch(void* const* d_in, const int* in_sizes, int n_in,
                              void* d_out, int out_size)
{
    const float* inputs = (const float*)d_in[0];
    const float* h0     = (const float*)d_in[1];
    const float* c0     = (const float*)d_in[2];
    const float* W1     = (const float*)d_in[3];
    const float* b1     = (const float*)d_in[4];
    const float* W_ih   = (const float*)d_in[5];
    const float* W_hh   = (const float*)d_in[6];
    const float* b_ih   = (const float*)d_in[7];
    const float* b_hh   = (const float*)d_in[8];
    const float* W_out  = (const float*)d_in[9];
    const float* b_out  = (const float*)d_in[10];

    float* out = (float*)d_out;
    float* hT  = out + TT * BB;
    float* cT  = hT + BB * HH;

    __half *pinc, *pxc, *pw1c, *pwihc, *pwhhc, *phc;
    float *pxg, *pbias;
    cudaGetSymbolAddress((void**)&pinc,  g_inc);
    cudaGetSymbolAddress((void**)&pxc,   g_xc);
    cudaGetSymbolAddress((void**)&pw1c,  g_w1c);
    cudaGetSymbolAddress((void**)&pwihc, g_wihc);
    cudaGetSymbolAddress((void**)&pwhhc, g_whhc);
    cudaGetSymbolAddress((void**)&phc,   g_hc);
    cudaGetSymbolAddress((void**)&pxg,   g_xg);
    cudaGetSymbolAddress((void**)&pbias, g_bias);

    cudaFuncSetAttribute(gemm_mma<0>, cudaFuncAttributeMaxDynamicSharedMemorySize, SMEM_BIG);
    cudaFuncSetAttribute(gemm_mma<1>, cudaFuncAttributeMaxDynamicSharedMemorySize, SMEM_BIG);
    cudaFuncSetAttribute(rec_step_k,  cudaFuncAttributeMaxDynamicSharedMemorySize, SMEM_REC);

    // conversions
    split_k<<<(32768 * 512) / 256, 256>>>(inputs, pinc, 32768, 512);
    split_hi_k<<<(1024 * 512) / 256, 256>>>(W1, pw1c, 1024, 512);
    split_perm_hi_k<<<(4096 * 1024) / 256, 256>>>(W_ih, pwihc);
    split_perm_hi_k<<<(4096 * 1024) / 256, 256>>>(W_hh, pwhhc);
    combine_bias_k<<<GG / 256, 256>>>(b_ih, b_hh);
    init_state_k<<<(BB * HH) / 256, 256>>>(h0, c0);
    out_init_k<<<(TT * BB) / 256, 256>>>(out, b_out);

    // GEMM1: x = relu(inputs @ W1^T + b1) -> split store g_xc  (2-pass, C=8)
    {
        dim3 grid(HH / 128, 32768 / 128);
        gemm_mma<0><<<grid, 256, SMEM_BIG>>>(pinc, pw1c, b1, nullptr, pxc, 32768, HH, 8);
    }
    // GEMM2: xg' = x @ W_ih'^T + bias' -> g_xg  (2-pass, C=16)
    {
        dim3 grid(GG / 128, 32768 / 128);
        gemm_mma<1><<<grid, 256, SMEM_BIG>>>(pxc, pwihc, pbias, pxg, nullptr, 32768, GG, 16);
    }
    // fused recurrence: 1 kernel per step (2-pass fp16)
    {
        dim3 grid(GG / 64, BB / 128);
        for (int t = 0; t < TT; t++) {
            rec_step_k<<<grid, 256, SMEM_REC>>>(
                phc + (t & 1) * HSPLIT, phc + ((t + 1) & 1) * HSPLIT,
                pwhhc, pxg + (size_t)t * BB * GG, W_out, out, hT, cT, t);
        }
    }
}

// round 8
// speedup vs baseline: 2.2811x; 1.6414x over previous
#include <cuda_runtime.h>
#include <cuda_fp16.h>
#include <math.h>
#include <stdint.h>

#define TT 128
#define BB 256
#define DD 512
#define HH 1024
#define GG 4096   // 4*H

// ===================== scratch (static device globals) ======================
__device__ __align__(16) __half g_inc [(size_t)16 * 32768 * 64]; // inputs hi+lo (C=8)
__device__ __align__(16) __half g_xc  [(size_t)16 * 32768 * 64]; // x hi only   (C=16)
__device__ __align__(16) __half g_w1c [(size_t)8  * 1024  * 64]; // W1 hi only
__device__ __align__(16) __half g_wihc[(size_t)16 * 4096  * 64]; // W_ih hi (gate-perm)
__device__ __align__(16) __half g_whhc[(size_t)16 * 4096  * 64]; // W_hh hi (gate-perm)
#define HSPLIT ((size_t)16 * 256 * 64)
__device__ __align__(16) __half g_hc  [2 * HSPLIT];              // h hi, ping-pong
__device__ __align__(16) float g_xg[(size_t)TT * BB * GG];       // gate-perm cols
__device__ __align__(16) float g_c[BB * HH];
__device__ __align__(16) float g_bias[GG];                       // gate-perm

// ===================== PTX helpers ==========================================
__device__ __forceinline__ uint32_t smem_u32(const void* p) {
    return (uint32_t)__cvta_generic_to_shared(p);
}
__device__ __forceinline__ void cp_async16(uint32_t dst, const void* src) {
    asm volatile("cp.async.cg.shared.global [%0], [%1], 16;" :: "r"(dst), "l"(src));
}
__device__ __forceinline__ void cp_commit() {
    asm volatile("cp.async.commit_group;" ::: "memory");
}
template<int N>
__device__ __forceinline__ void cp_wait() {
    asm volatile("cp.async.wait_group %0;" :: "n"(N) : "memory");
}
__device__ __forceinline__ void ldsm_x4(uint32_t& r0, uint32_t& r1, uint32_t& r2, uint32_t& r3,
                                        uint32_t addr) {
    asm volatile("ldmatrix.sync.aligned.m8n8.x4.shared.b16 {%0,%1,%2,%3}, [%4];"
                 : "=r"(r0), "=r"(r1), "=r"(r2), "=r"(r3) : "r"(addr));
}
__device__ __forceinline__ void mma16816(float* c, const uint32_t* a, const uint32_t* b) {
    asm volatile(
        "mma.sync.aligned.m16n8k16.row.col.f32.f16.f16.f32 "
        "{%0,%1,%2,%3}, {%4,%5,%6,%7}, {%8,%9}, {%0,%1,%2,%3};"
        : "+f"(c[0]), "+f"(c[1]), "+f"(c[2]), "+f"(c[3])
        : "r"(a[0]), "r"(a[1]), "r"(a[2]), "r"(a[3]), "r"(b[0]), "r"(b[1]));
}

__device__ __forceinline__ void split2(float v, __half& hi, __half& lo) {
    hi = __float2half_rn(v);
    lo = __float2half_rn(v - __half2float(hi));
}

__device__ __forceinline__ void store_hi(__half* dst, int M, int m, int n, float v) {
    const int chunk = n >> 6, col = n & 63;
    dst[((size_t)chunk * M + m) * 64 + col] = __float2half_rn(v);
}

// chunk loader: A tile RA rows, B tile RB rows, 128B rows, XOR-swizzled
#define LOAD_CHUNK(A_, B_, M_, N_, mB_, nB_, RA_, RB_, ac_, bc_, dA_)             \
    do {                                                                          \
        const char* As_ = (const char*)((A_) + ((size_t)(ac_) * (M_) + (mB_)) * 64);\
        const char* Bs_ = (const char*)((B_) + ((size_t)(bc_) * (N_) + (nB_)) * 64);\
        const uint32_t dB_ = (dA_) + (RA_) * 128u;                                \
        _Pragma("unroll")                                                         \
        for (int q_ = 0; q_ < (RA_) / 32; q_++) {                                 \
            const int e_ = tid + q_ * 256;                                        \
            const int r_ = e_ >> 3, s_ = e_ & 7;                                  \
            const uint32_t off_ = r_ * 128 + (((uint32_t)(s_ ^ (r_ & 7))) << 4);  \
            cp_async16((dA_) + off_, As_ + r_ * 128 + s_ * 16);                   \
        }                                                                         \
        _Pragma("unroll")                                                         \
        for (int q_ = 0; q_ < (RB_) / 32; q_++) {                                 \
            const int e_ = tid + q_ * 256;                                        \
            const int r_ = e_ >> 3, s_ = e_ & 7;                                  \
            const uint32_t off_ = r_ * 128 + (((uint32_t)(s_ ^ (r_ & 7))) << 4);  \
            cp_async16(dB_ + off_, Bs_ + r_ * 128 + s_ * 16);                     \
        }                                                                         \
    } while (0)

// pass map: p0 (A hi, B hi), p1 (A lo, B hi)
__device__ __forceinline__ void chunk_map2(int i, int C, int& ac, int& bc) {
    const int p = i / C, ci = i - p * C;
    ac = (p == 1) ? C + ci : ci;
    bc = ci;
}

// ===================== big GEMMs (BM=BN=128, 2 CTA/SM) =======================
// PASSES: 1 => A hi only; 2 => A hi+lo.  B always hi.
// MODE 0: v=relu(v+aux[n]) -> hi store; MODE 1: v=v+aux[n] -> outF
template<int MODE, int PASSES>
__global__ __launch_bounds__(256, 2)
void gemm_mma(const __half* __restrict__ A, const __half* __restrict__ B,
              const float* __restrict__ aux, float* __restrict__ outF,
              __half* __restrict__ outSplit, int M, int N, int C)
{
    extern __shared__ char smraw[];
    const uint32_t sbase = smem_u32(smraw);   // [2 bufs][A 16KB | B 16KB]

    const int tid  = threadIdx.x;
    const int lane = tid & 31;
    const int wid  = tid >> 5;
    const int wm   = wid & 3;
    const int wn   = wid >> 2;
    const int mBase = blockIdx.y * 128;
    const int nBase = blockIdx.x * 128;
    const int NIT = PASSES * C;

    float c[2][8][4];
#pragma unroll
    for (int i = 0; i < 2; i++)
#pragma unroll
        for (int j = 0; j < 8; j++)
#pragma unroll
            for (int k = 0; k < 4; k++) c[i][j][k] = 0.0f;

    const int lrow_a = ((lane >> 3) & 1) * 8 + (lane & 7);
    const int lrow_b = (lane >> 4) * 8 + (lane & 7);
    const int lxor   = lane & 7;
    const int ahalf  = lane >> 4;
    const int bhalf  = (lane >> 3) & 1;

    {
        int ac, bc; chunk_map2(0, C, ac, bc);
        LOAD_CHUNK(A, B, M, N, mBase, nBase, 128, 128, ac, bc, sbase);
        cp_commit();
    }

    for (int i = 0; i < NIT; i++) {
        const int buf = i & 1;
        if (i + 1 < NIT) {
            int ac, bc; chunk_map2(i + 1, C, ac, bc);
            LOAD_CHUNK(A, B, M, N, mBase, nBase, 128, 128, ac, bc,
                       sbase + ((i + 1) & 1) * 32768u);
            cp_commit();
            cp_wait<1>();
        } else {
            cp_wait<0>();
        }
        __syncthreads();

        const uint32_t aTile = sbase + buf * 32768u;
        const uint32_t bTile = aTile + 16384u;
#pragma unroll
        for (int kk = 0; kk < 4; kk++) {
            uint32_t a[2][4], b[8][2];
#pragma unroll
            for (int mt = 0; mt < 2; mt++) {
                const int row = wm * 32 + mt * 16 + lrow_a;
                const uint32_t addr = aTile + row * 128 +
                    (((uint32_t)((kk * 2 + ahalf) ^ lxor)) << 4);
                ldsm_x4(a[mt][0], a[mt][1], a[mt][2], a[mt][3], addr);
            }
#pragma unroll
            for (int bt = 0; bt < 4; bt++) {
                const int row = wn * 64 + bt * 16 + lrow_b;
                const uint32_t addr = bTile + row * 128 +
                    (((uint32_t)((kk * 2 + bhalf) ^ lxor)) << 4);
                uint32_t r0, r1, r2, r3;
                ldsm_x4(r0, r1, r2, r3, addr);
                b[2 * bt][0] = r0;     b[2 * bt][1] = r1;
                b[2 * bt + 1][0] = r2; b[2 * bt + 1][1] = r3;
            }
#pragma unroll
            for (int mt = 0; mt < 2; mt++)
#pragma unroll
                for (int nt = 0; nt < 8; nt++)
                    mma16816(c[mt][nt], a[mt], b[nt]);
        }
        __syncthreads();
    }

    const int g  = lane >> 2;
    const int tg = lane & 3;
#pragma unroll
    for (int mt = 0; mt < 2; mt++) {
        const int m0 = mBase + wm * 32 + mt * 16 + g;
#pragma unroll
        for (int nt = 0; nt < 8; nt++) {
            const int n0 = nBase + wn * 64 + nt * 8 + tg * 2;
#pragma unroll
            for (int half = 0; half < 2; half++) {
                const int m = m0 + half * 8;
                const float v0 = c[mt][nt][half * 2 + 0];
                const float v1 = c[mt][nt][half * 2 + 1];
                if (MODE == 0) {
                    store_hi(outSplit, M, m, n0,     fmaxf(v0 + aux[n0],     0.0f));
                    store_hi(outSplit, M, m, n0 + 1, fmaxf(v1 + aux[n0 + 1], 0.0f));
                } else {
                    float2 r = make_float2(v0 + aux[n0], v1 + aux[n0 + 1]);
                    *(float2*)(outF + (size_t)m * N + n0) = r;
                }
            }
        }
    }
}

// ===================== fused recurrence step (1-pass fp16) ===================
// gates = fp16(h) @ fp16(Whh)'^T + xg'(t)
#define GATE_W 68
__device__ __forceinline__ float sigf(float x) { return 1.0f / (1.0f + __expf(-x)); }

__global__ __launch_bounds__(256)
void rec_step_k(const __half* __restrict__ hcR, __half* __restrict__ hcW,
                const __half* __restrict__ whh, const float* __restrict__ xg,
                const float* __restrict__ W_out,
                float* __restrict__ out, float* __restrict__ hT, float* __restrict__ cT,
                int t)
{
    extern __shared__ char smraw[];
    const uint32_t sbase = smem_u32(smraw);   // [2 bufs][A 16KB | B 8KB] = 48KB
    float* gate_sm = (float*)smraw;

    const int tid  = threadIdx.x;
    const int lane = tid & 31;
    const int wid  = tid >> 5;
    const int wm   = wid & 3;
    const int wn   = wid >> 2;
    const int nBase = blockIdx.x * 64;
    const int mBase = blockIdx.y * 128;
    const int NIT = 16;   // 1 pass, C=16

    float c[2][4][4];
#pragma unroll
    for (int i = 0; i < 2; i++)
#pragma unroll
        for (int j = 0; j < 4; j++)
#pragma unroll
            for (int k = 0; k < 4; k++) c[i][j][k] = 0.0f;

    const int lrow_a = ((lane >> 3) & 1) * 8 + (lane & 7);
    const int lrow_b = (lane >> 4) * 8 + (lane & 7);
    const int lxor   = lane & 7;
    const int ahalf  = lane >> 4;
    const int bhalf  = (lane >> 3) & 1;

    LOAD_CHUNK(hcR, whh, 256, 4096, mBase, nBase, 128, 64, 0, 0, sbase);
    cp_commit();

    for (int i = 0; i < NIT; i++) {
        const int buf = i & 1;
        if (i + 1 < NIT) {
            LOAD_CHUNK(hcR, whh, 256, 4096, mBase, nBase, 128, 64, i + 1, i + 1,
                       sbase + ((i + 1) & 1) * 24576u);
            cp_commit();
            cp_wait<1>();
        } else {
            cp_wait<0>();
        }
        __syncthreads();

        const uint32_t aTile = sbase + buf * 24576u;
        const uint32_t bTile = aTile + 16384u;
#pragma unroll
        for (int kk = 0; kk < 4; kk++) {
            uint32_t a[2][4], b[4][2];
#pragma unroll
            for (int mt = 0; mt < 2; mt++) {
                const int row = wm * 32 + mt * 16 + lrow_a;
                const uint32_t addr = aTile + row * 128 +
                    (((uint32_t)((kk * 2 + ahalf) ^ lxor)) << 4);
                ldsm_x4(a[mt][0], a[mt][1], a[mt][2], a[mt][3], addr);
            }
#pragma unroll
            for (int bt = 0; bt < 2; bt++) {
                const int row = wn * 32 + bt * 16 + lrow_b;
                const uint32_t addr = bTile + row * 128 +
                    (((uint32_t)((kk * 2 + bhalf) ^ lxor)) << 4);
                uint32_t r0, r1, r2, r3;
                ldsm_x4(r0, r1, r2, r3, addr);
                b[2 * bt][0] = r0;     b[2 * bt][1] = r1;
                b[2 * bt + 1][0] = r2; b[2 * bt + 1][1] = r3;
            }
#pragma unroll
            for (int mt = 0; mt < 2; mt++)
#pragma unroll
                for (int nt = 0; nt < 4; nt++)
                    mma16816(c[mt][nt], a[mt], b[nt]);
        }
        __syncthreads();
    }

    const int g  = lane >> 2;
    const int tg = lane & 3;
#pragma unroll
    for (int mt = 0; mt < 2; mt++) {
#pragma unroll
        for (int nt = 0; nt < 4; nt++) {
            const int col = wn * 32 + nt * 8 + tg * 2;
#pragma unroll
            for (int half = 0; half < 2; half++) {
                const int row = wm * 32 + mt * 16 + g + half * 8;
                const float* xp = xg + (size_t)(mBase + row) * GG + nBase + col;
                gate_sm[row * GATE_W + col]     = c[mt][nt][half * 2 + 0] + xp[0];
                gate_sm[row * GATE_W + col + 1] = c[mt][nt][half * 2 + 1] + xp[1];
            }
        }
    }
    __syncthreads();

    const int bloc = tid >> 1;
    const int b = mBase + bloc;
    const int jh = (tid & 1) * 8;
    float osum = 0.0f;
#pragma unroll
    for (int jj = 0; jj < 8; jj++) {
        const int jloc = jh + jj;
        const int j = (nBase >> 2) + jloc;
        const float4 gt = *(const float4*)&gate_sm[bloc * GATE_W + jloc * 4];
        const float ig = sigf(gt.x);
        const float fg = sigf(gt.y);
        const float gg = tanhf(gt.z);
        const float og = sigf(gt.w);
        const float cc = fg * g_c[b * HH + j] + ig * gg;
        const float h  = og * tanhf(cc);
        g_c[b * HH + j] = cc;

        const int chunk = j >> 6, col = j & 63;
        hcW[((size_t)chunk * BB + b) * 64 + col] = __float2half_rn(h);

        osum += h * W_out[j];
        if (t == TT - 1) { hT[b * HH + j] = h; cT[b * HH + j] = cc; }
    }
    atomicAdd(&out[t * BB + b], osum);
}

// ===================== conversion / pointwise kernels ========================
__global__ void split_k(const float* __restrict__ src, __half* __restrict__ dst,
                        int R, int K)
{
    const size_t i = (size_t)blockIdx.x * blockDim.x + threadIdx.x;
    const int r = (int)(i / K);
    const int k = (int)(i - (size_t)r * K);
    __half hi, lo; split2(src[i], hi, lo);
    const int C = K >> 6;
    const int chunk = k >> 6, col = k & 63;
    dst[((size_t)chunk * R + r) * 64 + col] = hi;
    dst[((size_t)(C + chunk) * R + r) * 64 + col] = lo;
}

__global__ void split_hi_k(const float* __restrict__ src, __half* __restrict__ dst,
                           int R, int K)
{
    const size_t i = (size_t)blockIdx.x * blockDim.x + threadIdx.x;
    const int r = (int)(i / K);
    const int k = (int)(i - (size_t)r * K);
    const int chunk = k >> 6, col = k & 63;
    dst[((size_t)chunk * R + r) * 64 + col] = __float2half_rn(src[i]);
}

// gate-permuted, hi-only: dest row r' = j*4+g  (W_ih and W_hh)
__global__ void split_perm_hi_k(const float* __restrict__ src, __half* __restrict__ dst)
{
    const size_t i = (size_t)blockIdx.x * blockDim.x + threadIdx.x;
    const int r = (int)(i >> 10);
    const int k = (int)(i & 1023);
    const int gt = r >> 10, j = r & 1023;
    const int rp = j * 4 + gt;
    const int chunk = k >> 6, col = k & 63;
    dst[((size_t)chunk * 4096 + rp) * 64 + col] = __float2half_rn(src[i]);
}

__global__ void combine_bias_k(const float* __restrict__ b_ih, const float* __restrict__ b_hh)
{
    int i = blockIdx.x * blockDim.x + threadIdx.x;
    if (i < GG) {
        const int gt = i & 3, j = i >> 2;
        const int s = gt * HH + j;
        g_bias[i] = b_ih[s] + b_hh[s];
    }
}

__global__ void init_state_k(const float* __restrict__ h0, const float* __restrict__ c0)
{
    const int i = blockIdx.x * blockDim.x + threadIdx.x;
    const int b = i >> 10, j = i & 1023;
    g_c[i] = c0[i];
    const int chunk = j >> 6, col = j & 63;
    g_hc[((size_t)chunk * BB + b) * 64 + col] = __float2half_rn(h0[i]);
}

__global__ void out_init_k(float* __restrict__ out, const float* __restrict__ b_out)
{
    const int i = blockIdx.x * blockDim.x + threadIdx.x;
    if (i < TT * BB) out[i] = b_out[0];
}

// ===================== launch ================================================
#define SMEM_BIG 65536
#define SMEM_REC 49152

extern "C" void kernel_launch(void* const* d_in, const int* in_sizes, int n_in,
                              void* d_out, int out_size)
{
    const float* inputs = (const float*)d_in[0];
    const float* h0     = (const float*)d_in[1];
    const float* c0     = (const float*)d_in[2];
    const float* W1     = (const float*)d_in[3];
    const float* b1     = (const float*)d_in[4];
    const float* W_ih   = (const float*)d_in[5];
    const float* W_hh   = (const float*)d_in[6];
    const float* b_ih   = (const float*)d_in[7];
    const float* b_hh   = (const float*)d_in[8];
    const float* W_out  = (const float*)d_in[9];
    const float* b_out  = (const float*)d_in[10];

    float* out = (float*)d_out;
    float* hT  = out + TT * BB;
    float* cT  = hT + BB * HH;

    __half *pinc, *pxc, *pw1c, *pwihc, *pwhhc, *phc;
    float *pxg, *pbias;
    cudaGetSymbolAddress((void**)&pinc,  g_inc);
    cudaGetSymbolAddress((void**)&pxc,   g_xc);
    cudaGetSymbolAddress((void**)&pw1c,  g_w1c);
    cudaGetSymbolAddress((void**)&pwihc, g_wihc);
    cudaGetSymbolAddress((void**)&pwhhc, g_whhc);
    cudaGetSymbolAddress((void**)&phc,   g_hc);
    cudaGetSymbolAddress((void**)&pxg,   g_xg);
    cudaGetSymbolAddress((void**)&pbias, g_bias);

    cudaFuncSetAttribute((const void*)gemm_mma<0, 2>, cudaFuncAttributeMaxDynamicSharedMemorySize, SMEM_BIG);
    cudaFuncSetAttribute((const void*)gemm_mma<1, 1>, cudaFuncAttributeMaxDynamicSharedMemorySize, SMEM_BIG);
    cudaFuncSetAttribute((const void*)rec_step_k,     cudaFuncAttributeMaxDynamicSharedMemorySize, SMEM_REC);

    // conversions
    split_k<<<(32768 * 512) / 256, 256>>>(inputs, pinc, 32768, 512);
    split_hi_k<<<(1024 * 512) / 256, 256>>>(W1, pw1c, 1024, 512);
    split_perm_hi_k<<<(4096 * 1024) / 256, 256>>>(W_ih, pwihc);
    split_perm_hi_k<<<(4096 * 1024) / 256, 256>>>(W_hh, pwhhc);
    combine_bias_k<<<GG / 256, 256>>>(b_ih, b_hh);
    init_state_k<<<(BB * HH) / 256, 256>>>(h0, c0);
    out_init_k<<<(TT * BB) / 256, 256>>>(out, b_out);

    // GEMM1: x = relu(inputs @ W1^T + b1) -> hi store g_xc  (2-pass, C=8)
    {
        dim3 grid(HH / 128, 32768 / 128);
        gemm_mma<0, 2><<<grid, 256, SMEM_BIG>>>(pinc, pw1c, b1, nullptr, pxc, 32768, HH, 8);
    }
    // GEMM2: xg' = x_hi @ W_ih_hi'^T + bias' -> g_xg  (1-pass, C=16)
    {
        dim3 grid(GG / 128, 32768 / 128);
        gemm_mma<1, 1><<<grid, 256, SMEM_BIG>>>(pxc, pwihc, pbias, pxg, nullptr, 32768, GG, 16);
    }
    // fused recurrence: 1 kernel per step (1-pass fp16)
    {
        dim3 grid(GG / 64, BB / 128);
        for (int t = 0; t < TT; t++) {
            rec_step_k<<<grid, 256, SMEM_REC>>>(
                phc + (t & 1) * HSPLIT, phc + ((t + 1) & 1) * HSPLIT,
                pwhhc, pxg + (size_t)t * BB * GG, W_out, out, hT, cT, t);
        }
    }
}

// round 9
// speedup vs baseline: 2.4691x; 1.0824x over previous
#include <cuda_runtime.h>
#include <cuda_fp16.h>
#include <math.h>
#include <stdint.h>

#define TT 128
#define BB 256
#define DD 512
#define HH 1024
#define GG 4096   // 4*H

// ===================== scratch (static device globals) ======================
__device__ __align__(16) __half g_inc [(size_t)16 * 32768 * 64]; // inputs hi+lo (C=8)
__device__ __align__(16) __half g_xc  [(size_t)16 * 32768 * 64]; // x hi only   (C=16)
__device__ __align__(16) __half g_w1c [(size_t)8  * 1024  * 64]; // W1 hi only
__device__ __align__(16) __half g_wihc[(size_t)16 * 4096  * 64]; // W_ih hi (gate-perm)
__device__ __align__(16) __half g_whhc[(size_t)16 * 4096  * 64]; // W_hh hi (gate-perm)
#define HSPLIT ((size_t)16 * 256 * 64)
__device__ __align__(16) __half g_hc  [2 * HSPLIT];              // h hi, ping-pong
__device__ __align__(16) float g_xg[(size_t)TT * BB * GG];       // gate-perm cols
__device__ __align__(16) float g_bias[GG];                       // gate-perm
__device__ int g_bar;                                            // global step barrier

// ===================== PTX helpers ==========================================
__device__ __forceinline__ uint32_t smem_u32(const void* p) {
    return (uint32_t)__cvta_generic_to_shared(p);
}
__device__ __forceinline__ void cp_async16(uint32_t dst, const void* src) {
    asm volatile("cp.async.cg.shared.global [%0], [%1], 16;" :: "r"(dst), "l"(src));
}
__device__ __forceinline__ void cp_commit() {
    asm volatile("cp.async.commit_group;" ::: "memory");
}
template<int N>
__device__ __forceinline__ void cp_wait() {
    asm volatile("cp.async.wait_group %0;" :: "n"(N) : "memory");
}
__device__ __forceinline__ void ldsm_x4(uint32_t& r0, uint32_t& r1, uint32_t& r2, uint32_t& r3,
                                        uint32_t addr) {
    asm volatile("ldmatrix.sync.aligned.m8n8.x4.shared.b16 {%0,%1,%2,%3}, [%4];"
                 : "=r"(r0), "=r"(r1), "=r"(r2), "=r"(r3) : "r"(addr));
}
__device__ __forceinline__ void mma16816(float* c, const uint32_t* a, const uint32_t* b) {
    asm volatile(
        "mma.sync.aligned.m16n8k16.row.col.f32.f16.f16.f32 "
        "{%0,%1,%2,%3}, {%4,%5,%6,%7}, {%8,%9}, {%0,%1,%2,%3};"
        : "+f"(c[0]), "+f"(c[1]), "+f"(c[2]), "+f"(c[3])
        : "r"(a[0]), "r"(a[1]), "r"(a[2]), "r"(a[3]), "r"(b[0]), "r"(b[1]));
}

__device__ __forceinline__ void split2(float v, __half& hi, __half& lo) {
    hi = __float2half_rn(v);
    lo = __float2half_rn(v - __half2float(hi));
}

__device__ __forceinline__ void store_hi(__half* dst, int M, int m, int n, float v) {
    const int chunk = n >> 6, col = n & 63;
    dst[((size_t)chunk * M + m) * 64 + col] = __float2half_rn(v);
}

// chunk loader: A tile RA rows, B tile RB rows, 128B rows, XOR-swizzled
#define LOAD_CHUNK(A_, B_, M_, N_, mB_, nB_, RA_, RB_, ac_, bc_, dA_)             \
    do {                                                                          \
        const char* As_ = (const char*)((A_) + ((size_t)(ac_) * (M_) + (mB_)) * 64);\
        const char* Bs_ = (const char*)((B_) + ((size_t)(bc_) * (N_) + (nB_)) * 64);\
        const uint32_t dB_ = (dA_) + (RA_) * 128u;                                \
        _Pragma("unroll")                                                         \
        for (int q_ = 0; q_ < (RA_) / 32; q_++) {                                 \
            const int e_ = tid + q_ * 256;                                        \
            const int r_ = e_ >> 3, s_ = e_ & 7;                                  \
            const uint32_t off_ = r_ * 128 + (((uint32_t)(s_ ^ (r_ & 7))) << 4);  \
            cp_async16((dA_) + off_, As_ + r_ * 128 + s_ * 16);                   \
        }                                                                         \
        _Pragma("unroll")                                                         \
        for (int q_ = 0; q_ < (RB_) / 32; q_++) {                                 \
            const int e_ = tid + q_ * 256;                                        \
            const int r_ = e_ >> 3, s_ = e_ & 7;                                  \
            const uint32_t off_ = r_ * 128 + (((uint32_t)(s_ ^ (r_ & 7))) << 4);  \
            cp_async16(dB_ + off_, Bs_ + r_ * 128 + s_ * 16);                     \
        }                                                                         \
    } while (0)

// pass map: p0 (A hi, B hi), p1 (A lo, B hi)
__device__ __forceinline__ void chunk_map2(int i, int C, int& ac, int& bc) {
    const int p = i / C, ci = i - p * C;
    ac = (p == 1) ? C + ci : ci;
    bc = ci;
}

// ===================== big GEMMs (BM=BN=128, 2 CTA/SM) =======================
template<int MODE, int PASSES>
__global__ __launch_bounds__(256, 2)
void gemm_mma(const __half* __restrict__ A, const __half* __restrict__ B,
              const float* __restrict__ aux, float* __restrict__ outF,
              __half* __restrict__ outSplit, int M, int N, int C)
{
    extern __shared__ char smraw[];
    const uint32_t sbase = smem_u32(smraw);

    const int tid  = threadIdx.x;
    const int lane = tid & 31;
    const int wid  = tid >> 5;
    const int wm   = wid & 3;
    const int wn   = wid >> 2;
    const int mBase = blockIdx.y * 128;
    const int nBase = blockIdx.x * 128;
    const int NIT = PASSES * C;

    float c[2][8][4];
#pragma unroll
    for (int i = 0; i < 2; i++)
#pragma unroll
        for (int j = 0; j < 8; j++)
#pragma unroll
            for (int k = 0; k < 4; k++) c[i][j][k] = 0.0f;

    const int lrow_a = ((lane >> 3) & 1) * 8 + (lane & 7);
    const int lrow_b = (lane >> 4) * 8 + (lane & 7);
    const int lxor   = lane & 7;
    const int ahalf  = lane >> 4;
    const int bhalf  = (lane >> 3) & 1;

    {
        int ac, bc; chunk_map2(0, C, ac, bc);
        LOAD_CHUNK(A, B, M, N, mBase, nBase, 128, 128, ac, bc, sbase);
        cp_commit();
    }

    for (int i = 0; i < NIT; i++) {
        const int buf = i & 1;
        if (i + 1 < NIT) {
            int ac, bc; chunk_map2(i + 1, C, ac, bc);
            LOAD_CHUNK(A, B, M, N, mBase, nBase, 128, 128, ac, bc,
                       sbase + ((i + 1) & 1) * 32768u);
            cp_commit();
            cp_wait<1>();
        } else {
            cp_wait<0>();
        }
        __syncthreads();

        const uint32_t aTile = sbase + buf * 32768u;
        const uint32_t bTile = aTile + 16384u;
#pragma unroll
        for (int kk = 0; kk < 4; kk++) {
            uint32_t a[2][4], b[8][2];
#pragma unroll
            for (int mt = 0; mt < 2; mt++) {
                const int row = wm * 32 + mt * 16 + lrow_a;
                const uint32_t addr = aTile + row * 128 +
                    (((uint32_t)((kk * 2 + ahalf) ^ lxor)) << 4);
                ldsm_x4(a[mt][0], a[mt][1], a[mt][2], a[mt][3], addr);
            }
#pragma unroll
            for (int bt = 0; bt < 4; bt++) {
                const int row = wn * 64 + bt * 16 + lrow_b;
                const uint32_t addr = bTile + row * 128 +
                    (((uint32_t)((kk * 2 + bhalf) ^ lxor)) << 4);
                uint32_t r0, r1, r2, r3;
                ldsm_x4(r0, r1, r2, r3, addr);
                b[2 * bt][0] = r0;     b[2 * bt][1] = r1;
                b[2 * bt + 1][0] = r2; b[2 * bt + 1][1] = r3;
            }
#pragma unroll
            for (int mt = 0; mt < 2; mt++)
#pragma unroll
                for (int nt = 0; nt < 8; nt++)
                    mma16816(c[mt][nt], a[mt], b[nt]);
        }
        __syncthreads();
    }

    const int g  = lane >> 2;
    const int tg = lane & 3;
#pragma unroll
    for (int mt = 0; mt < 2; mt++) {
        const int m0 = mBase + wm * 32 + mt * 16 + g;
#pragma unroll
        for (int nt = 0; nt < 8; nt++) {
            const int n0 = nBase + wn * 64 + nt * 8 + tg * 2;
#pragma unroll
            for (int half = 0; half < 2; half++) {
                const int m = m0 + half * 8;
                const float v0 = c[mt][nt][half * 2 + 0];
                const float v1 = c[mt][nt][half * 2 + 1];
                if (MODE == 0) {
                    store_hi(outSplit, M, m, n0,     fmaxf(v0 + aux[n0],     0.0f));
                    store_hi(outSplit, M, m, n0 + 1, fmaxf(v1 + aux[n0 + 1], 0.0f));
                } else {
                    float2 r = make_float2(v0 + aux[n0], v1 + aux[n0 + 1]);
                    *(float2*)(outF + (size_t)m * N + n0) = r;
                }
            }
        }
    }
}

// ===================== persistent fused recurrence ===========================
// 128 CTAs (all co-resident), global spin barrier between steps.
#define GATE_W 68
#define NCTAS 128
__device__ __forceinline__ float sigf(float x) { return 1.0f / (1.0f + __expf(-x)); }

__global__ __launch_bounds__(256, 1)
void rec_persist_k(__half* __restrict__ hc0, __half* __restrict__ hc1,
                   const __half* __restrict__ whh, const float* __restrict__ xg,
                   const float* __restrict__ W_out, const float* __restrict__ c0,
                   float* __restrict__ out, float* __restrict__ hT, float* __restrict__ cT)
{
    extern __shared__ char smraw[];
    const uint32_t sbase = smem_u32(smraw);   // [2 bufs][A 16KB | B 8KB] = 48KB
    float* gate_sm = (float*)smraw;

    const int tid  = threadIdx.x;
    const int lane = tid & 31;
    const int wid  = tid >> 5;
    const int wm   = wid & 3;
    const int wn   = wid >> 2;
    const int nBase = blockIdx.x * 64;
    const int mBase = blockIdx.y * 128;
    const int NIT = 16;

    const int lrow_a = ((lane >> 3) & 1) * 8 + (lane & 7);
    const int lrow_b = (lane >> 4) * 8 + (lane & 7);
    const int lxor   = lane & 7;
    const int ahalf  = lane >> 4;
    const int bhalf  = (lane >> 3) & 1;

    // per-thread persistent cell state + output weights (8 hidden units)
    const int bloc = tid >> 1;
    const int b = mBase + bloc;
    const int jh = (tid & 1) * 8;
    const int j0 = (nBase >> 2) + jh;
    float cc[8], wout[8];
#pragma unroll
    for (int jj = 0; jj < 8; jj++) {
        cc[jj]   = c0[b * HH + j0 + jj];
        wout[jj] = W_out[j0 + jj];
    }

    volatile int* barp = &g_bar;

    for (int t = 0; t < TT; t++) {
        const __half* hcR = (t & 1) ? hc1 : hc0;
        __half*       hcW = (t & 1) ? hc0 : hc1;
        const float*  xg_t = xg + (size_t)t * BB * GG;

        // prefetch this thread's xg slice (independent of h -> overlaps mainloop)
        float4 xr[8];
        const float4* xp = (const float4*)(xg_t + (size_t)b * GG + nBase) + jh;
#pragma unroll
        for (int jj = 0; jj < 8; jj++) xr[jj] = xp[jj];

        float c[2][4][4];
#pragma unroll
        for (int i = 0; i < 2; i++)
#pragma unroll
            for (int j = 0; j < 4; j++)
#pragma unroll
                for (int k = 0; k < 4; k++) c[i][j][k] = 0.0f;

        LOAD_CHUNK(hcR, whh, 256, 4096, mBase, nBase, 128, 64, 0, 0, sbase);
        cp_commit();

        for (int i = 0; i < NIT; i++) {
            const int buf = i & 1;
            if (i + 1 < NIT) {
                LOAD_CHUNK(hcR, whh, 256, 4096, mBase, nBase, 128, 64, i + 1, i + 1,
                           sbase + ((i + 1) & 1) * 24576u);
                cp_commit();
                cp_wait<1>();
            } else {
                cp_wait<0>();
            }
            __syncthreads();

            const uint32_t aTile = sbase + buf * 24576u;
            const uint32_t bTile = aTile + 16384u;
#pragma unroll
            for (int kk = 0; kk < 4; kk++) {
                uint32_t a[2][4], bfrag[4][2];
#pragma unroll
                for (int mt = 0; mt < 2; mt++) {
                    const int row = wm * 32 + mt * 16 + lrow_a;
                    const uint32_t addr = aTile + row * 128 +
                        (((uint32_t)((kk * 2 + ahalf) ^ lxor)) << 4);
                    ldsm_x4(a[mt][0], a[mt][1], a[mt][2], a[mt][3], addr);
                }
#pragma unroll
                for (int bt = 0; bt < 2; bt++) {
                    const int row = wn * 32 + bt * 16 + lrow_b;
                    const uint32_t addr = bTile + row * 128 +
                        (((uint32_t)((kk * 2 + bhalf) ^ lxor)) << 4);
                    uint32_t r0, r1, r2, r3;
                    ldsm_x4(r0, r1, r2, r3, addr);
                    bfrag[2 * bt][0] = r0;     bfrag[2 * bt][1] = r1;
                    bfrag[2 * bt + 1][0] = r2; bfrag[2 * bt + 1][1] = r3;
                }
#pragma unroll
                for (int mt = 0; mt < 2; mt++)
#pragma unroll
                    for (int nt = 0; nt < 4; nt++)
                        mma16816(c[mt][nt], a[mt], bfrag[nt]);
            }
            __syncthreads();
        }

        // stage MMA result into smem (xg added later from registers)
        const int g  = lane >> 2;
        const int tg = lane & 3;
#pragma unroll
        for (int mt = 0; mt < 2; mt++) {
#pragma unroll
            for (int nt = 0; nt < 4; nt++) {
                const int col = wn * 32 + nt * 8 + tg * 2;
#pragma unroll
                for (int half = 0; half < 2; half++) {
                    const int row = wm * 32 + mt * 16 + g + half * 8;
                    gate_sm[row * GATE_W + col]     = c[mt][nt][half * 2 + 0];
                    gate_sm[row * GATE_W + col + 1] = c[mt][nt][half * 2 + 1];
                }
            }
        }
        __syncthreads();

        // cell math (c held in registers across steps)
        float osum = 0.0f;
#pragma unroll
        for (int jj = 0; jj < 8; jj++) {
            const int jloc = jh + jj;
            const int j = (nBase >> 2) + jloc;
            const float4 mm = *(const float4*)&gate_sm[bloc * GATE_W + jloc * 4];
            const float ig = sigf(mm.x + xr[jj].x);
            const float fg = sigf(mm.y + xr[jj].y);
            const float gg = tanhf(mm.z + xr[jj].z);
            const float og = sigf(mm.w + xr[jj].w);
            cc[jj] = fg * cc[jj] + ig * gg;
            const float h = og * tanhf(cc[jj]);

            const int chunk = j >> 6, col = j & 63;
            hcW[((size_t)chunk * BB + b) * 64 + col] = __float2half_rn(h);
            osum += h * wout[jj];
            if (t == TT - 1) { hT[b * HH + j] = h; cT[b * HH + j] = cc[jj]; }
        }
        atomicAdd(&out[t * BB + b], osum);

        // global step barrier
        __threadfence();
        __syncthreads();
        if (tid == 0) {
            atomicAdd(&g_bar, 1);
            const int target = NCTAS * (t + 1);
            while (*barp < target) { __nanosleep(64); }
        }
        __syncthreads();
        __threadfence();
    }
}

// ===================== conversion / pointwise kernels ========================
__global__ void split_k(const float* __restrict__ src, __half* __restrict__ dst,
                        int R, int K)
{
    const size_t i = (size_t)blockIdx.x * blockDim.x + threadIdx.x;
    const int r = (int)(i / K);
    const int k = (int)(i - (size_t)r * K);
    __half hi, lo; split2(src[i], hi, lo);
    const int C = K >> 6;
    const int chunk = k >> 6, col = k & 63;
    dst[((size_t)chunk * R + r) * 64 + col] = hi;
    dst[((size_t)(C + chunk) * R + r) * 64 + col] = lo;
}

__global__ void split_hi_k(const float* __restrict__ src, __half* __restrict__ dst,
                           int R, int K)
{
    const size_t i = (size_t)blockIdx.x * blockDim.x + threadIdx.x;
    const int r = (int)(i / K);
    const int k = (int)(i - (size_t)r * K);
    const int chunk = k >> 6, col = k & 63;
    dst[((size_t)chunk * R + r) * 64 + col] = __float2half_rn(src[i]);
}

__global__ void split_perm_hi_k(const float* __restrict__ src, __half* __restrict__ dst)
{
    const size_t i = (size_t)blockIdx.x * blockDim.x + threadIdx.x;
    const int r = (int)(i >> 10);
    const int k = (int)(i & 1023);
    const int gt = r >> 10, j = r & 1023;
    const int rp = j * 4 + gt;
    const int chunk = k >> 6, col = k & 63;
    dst[((size_t)chunk * 4096 + rp) * 64 + col] = __float2half_rn(src[i]);
}

__global__ void combine_bias_k(const float* __restrict__ b_ih, const float* __restrict__ b_hh)
{
    int i = blockIdx.x * blockDim.x + threadIdx.x;
    if (i < GG) {
        const int gt = i & 3, j = i >> 2;
        const int s = gt * HH + j;
        g_bias[i] = b_ih[s] + b_hh[s];
    }
}

__global__ void init_state_k(const float* __restrict__ h0)
{
    const int i = blockIdx.x * blockDim.x + threadIdx.x;
    const int b = i >> 10, j = i & 1023;
    const int chunk = j >> 6, col = j & 63;
    g_hc[((size_t)chunk * BB + b) * 64 + col] = __float2half_rn(h0[i]);
}

__global__ void out_init_k(float* __restrict__ out, const float* __restrict__ b_out)
{
    const int i = blockIdx.x * blockDim.x + threadIdx.x;
    if (i == 0) g_bar = 0;
    if (i < TT * BB) out[i] = b_out[0];
}

// ===================== launch ================================================
#define SMEM_BIG 65536
#define SMEM_REC 49152

extern "C" void kernel_launch(void* const* d_in, const int* in_sizes, int n_in,
                              void* d_out, int out_size)
{
    const float* inputs = (const float*)d_in[0];
    const float* h0     = (const float*)d_in[1];
    const float* c0     = (const float*)d_in[2];
    const float* W1     = (const float*)d_in[3];
    const float* b1     = (const float*)d_in[4];
    const float* W_ih   = (const float*)d_in[5];
    const float* W_hh   = (const float*)d_in[6];
    const float* b_ih   = (const float*)d_in[7];
    const float* b_hh   = (const float*)d_in[8];
    const float* W_out  = (const float*)d_in[9];
    const float* b_out  = (const float*)d_in[10];

    float* out = (float*)d_out;
    float* hT  = out + TT * BB;
    float* cT  = hT + BB * HH;

    __half *pinc, *pxc, *pw1c, *pwihc, *pwhhc, *phc;
    float *pxg, *pbias;
    cudaGetSymbolAddress((void**)&pinc,  g_inc);
    cudaGetSymbolAddress((void**)&pxc,   g_xc);
    cudaGetSymbolAddress((void**)&pw1c,  g_w1c);
    cudaGetSymbolAddress((void**)&pwihc, g_wihc);
    cudaGetSymbolAddress((void**)&pwhhc, g_whhc);
    cudaGetSymbolAddress((void**)&phc,   g_hc);
    cudaGetSymbolAddress((void**)&pxg,   g_xg);
    cudaGetSymbolAddress((void**)&pbias, g_bias);

    cudaFuncSetAttribute((const void*)gemm_mma<0, 2>, cudaFuncAttributeMaxDynamicSharedMemorySize, SMEM_BIG);
    cudaFuncSetAttribute((const void*)gemm_mma<1, 1>, cudaFuncAttributeMaxDynamicSharedMemorySize, SMEM_BIG);
    cudaFuncSetAttribute((const void*)rec_persist_k,  cudaFuncAttributeMaxDynamicSharedMemorySize, SMEM_REC);

    // conversions
    split_k<<<(32768 * 512) / 256, 256>>>(inputs, pinc, 32768, 512);
    split_hi_k<<<(1024 * 512) / 256, 256>>>(W1, pw1c, 1024, 512);
    split_perm_hi_k<<<(4096 * 1024) / 256, 256>>>(W_ih, pwihc);
    split_perm_hi_k<<<(4096 * 1024) / 256, 256>>>(W_hh, pwhhc);
    combine_bias_k<<<GG / 256, 256>>>(b_ih, b_hh);
    init_state_k<<<(BB * HH) / 256, 256>>>(h0);
    out_init_k<<<(TT * BB) / 256, 256>>>(out, b_out);

    // GEMM1: x = relu(inputs @ W1^T + b1) -> hi store g_xc  (2-pass, C=8)
    {
        dim3 grid(HH / 128, 32768 / 128);
        gemm_mma<0, 2><<<grid, 256, SMEM_BIG>>>(pinc, pw1c, b1, nullptr, pxc, 32768, HH, 8);
    }
    // GEMM2: xg' = x_hi @ W_ih_hi'^T + bias' -> g_xg  (1-pass, C=16)
    {
        dim3 grid(GG / 128, 32768 / 128);
        gemm_mma<1, 1><<<grid, 256, SMEM_BIG>>>(pxc, pwihc, pbias, pxg, nullptr, 32768, GG, 16);
    }
    // persistent recurrence: single launch, 128 co-resident CTAs
    {
        dim3 grid(GG / 64, BB / 128);   // 64 x 2 = 128 CTAs
        rec_persist_k<<<grid, 256, SMEM_REC>>>(phc, phc + HSPLIT, pwhhc, pxg,
                                               W_out, c0, out, hT, cT);
    }
}

// round 10
// speedup vs baseline: 2.5205x; 1.0208x over previous
#include <cuda_runtime.h>
#include <cuda_fp16.h>
#include <math.h>
#include <stdint.h>

#define TT 128
#define BB 256
#define DD 512
#define HH 1024
#define GG 4096   // 4*H

// ===================== scratch (static device globals) ======================
__device__ __align__(16) __half g_inc [(size_t)8  * 32768 * 64]; // inputs hi (C=8)
__device__ __align__(16) __half g_xc  [(size_t)16 * 32768 * 64]; // x hi      (C=16)
__device__ __align__(16) __half g_w1c [(size_t)8  * 1024  * 64]; // W1 hi
__device__ __align__(16) __half g_wihc[(size_t)16 * 4096  * 64]; // W_ih hi (gate-perm)
__device__ __align__(16) __half g_whhc[(size_t)16 * 4096  * 64]; // W_hh hi (gate-perm)
#define HSPLIT ((size_t)16 * 256 * 64)
__device__ __align__(16) __half g_hc  [2 * HSPLIT];              // h hi, ping-pong
__device__ __align__(16) float g_xg[(size_t)TT * BB * GG];       // gate-perm cols
__device__ __align__(16) float g_bias[GG];                       // gate-perm
__device__ int g_bar;                                            // global step barrier

// ===================== PTX helpers ==========================================
__device__ __forceinline__ uint32_t smem_u32(const void* p) {
    return (uint32_t)__cvta_generic_to_shared(p);
}
__device__ __forceinline__ void cp_async16(uint32_t dst, const void* src) {
    asm volatile("cp.async.cg.shared.global [%0], [%1], 16;" :: "r"(dst), "l"(src));
}
__device__ __forceinline__ void cp_commit() {
    asm volatile("cp.async.commit_group;" ::: "memory");
}
template<int N>
__device__ __forceinline__ void cp_wait() {
    asm volatile("cp.async.wait_group %0;" :: "n"(N) : "memory");
}
__device__ __forceinline__ void ldsm_x4(uint32_t& r0, uint32_t& r1, uint32_t& r2, uint32_t& r3,
                                        uint32_t addr) {
    asm volatile("ldmatrix.sync.aligned.m8n8.x4.shared.b16 {%0,%1,%2,%3}, [%4];"
                 : "=r"(r0), "=r"(r1), "=r"(r2), "=r"(r3) : "r"(addr));
}
__device__ __forceinline__ void mma16816(float* c, const uint32_t* a, const uint32_t* b) {
    asm volatile(
        "mma.sync.aligned.m16n8k16.row.col.f32.f16.f16.f32 "
        "{%0,%1,%2,%3}, {%4,%5,%6,%7}, {%8,%9}, {%0,%1,%2,%3};"
        : "+f"(c[0]), "+f"(c[1]), "+f"(c[2]), "+f"(c[3])
        : "r"(a[0]), "r"(a[1]), "r"(a[2]), "r"(a[3]), "r"(b[0]), "r"(b[1]));
}

__device__ __forceinline__ void store_hi(__half* dst, int M, int m, int n, float v) {
    const int chunk = n >> 6, col = n & 63;
    dst[((size_t)chunk * M + m) * 64 + col] = __float2half_rn(v);
}

// chunk loader: A tile RA rows, B tile RB rows, 128B rows, XOR-swizzled
#define LOAD_CHUNK(A_, B_, M_, N_, mB_, nB_, RA_, RB_, ac_, bc_, dA_)             \
    do {                                                                          \
        const char* As_ = (const char*)((A_) + ((size_t)(ac_) * (M_) + (mB_)) * 64);\
        const char* Bs_ = (const char*)((B_) + ((size_t)(bc_) * (N_) + (nB_)) * 64);\
        const uint32_t dB_ = (dA_) + (RA_) * 128u;                                \
        _Pragma("unroll")                                                         \
        for (int q_ = 0; q_ < (RA_) / 32; q_++) {                                 \
            const int e_ = tid + q_ * 256;                                        \
            const int r_ = e_ >> 3, s_ = e_ & 7;                                  \
            const uint32_t off_ = r_ * 128 + (((uint32_t)(s_ ^ (r_ & 7))) << 4);  \
            cp_async16((dA_) + off_, As_ + r_ * 128 + s_ * 16);                   \
        }                                                                         \
        _Pragma("unroll")                                                         \
        for (int q_ = 0; q_ < (RB_) / 32; q_++) {                                 \
            const int e_ = tid + q_ * 256;                                        \
            const int r_ = e_ >> 3, s_ = e_ & 7;                                  \
            const uint32_t off_ = r_ * 128 + (((uint32_t)(s_ ^ (r_ & 7))) << 4);  \
            cp_async16(dB_ + off_, Bs_ + r_ * 128 + s_ * 16);                     \
        }                                                                         \
    } while (0)

// ===================== big GEMMs (BM=BN=128, 1-pass fp16, 2 CTA/SM) ==========
// MODE 0: v=relu(v+aux[n]) -> hi store; MODE 1: v=v+aux[n] -> outF
template<int MODE>
__global__ __launch_bounds__(256, 2)
void gemm_mma(const __half* __restrict__ A, const __half* __restrict__ B,
              const float* __restrict__ aux, float* __restrict__ outF,
              __half* __restrict__ outSplit, int M, int N, int C)
{
    extern __shared__ char smraw[];
    const uint32_t sbase = smem_u32(smraw);

    const int tid  = threadIdx.x;
    const int lane = tid & 31;
    const int wid  = tid >> 5;
    const int wm   = wid & 3;
    const int wn   = wid >> 2;
    const int mBase = blockIdx.y * 128;
    const int nBase = blockIdx.x * 128;
    const int NIT = C;

    float c[2][8][4];
#pragma unroll
    for (int i = 0; i < 2; i++)
#pragma unroll
        for (int j = 0; j < 8; j++)
#pragma unroll
            for (int k = 0; k < 4; k++) c[i][j][k] = 0.0f;

    const int lrow_a = ((lane >> 3) & 1) * 8 + (lane & 7);
    const int lrow_b = (lane >> 4) * 8 + (lane & 7);
    const int lxor   = lane & 7;
    const int ahalf  = lane >> 4;
    const int bhalf  = (lane >> 3) & 1;

    LOAD_CHUNK(A, B, M, N, mBase, nBase, 128, 128, 0, 0, sbase);
    cp_commit();

    for (int i = 0; i < NIT; i++) {
        const int buf = i & 1;
        if (i + 1 < NIT) {
            LOAD_CHUNK(A, B, M, N, mBase, nBase, 128, 128, i + 1, i + 1,
                       sbase + ((i + 1) & 1) * 32768u);
            cp_commit();
            cp_wait<1>();
        } else {
            cp_wait<0>();
        }
        __syncthreads();

        const uint32_t aTile = sbase + buf * 32768u;
        const uint32_t bTile = aTile + 16384u;
#pragma unroll
        for (int kk = 0; kk < 4; kk++) {
            uint32_t a[2][4], b[8][2];
#pragma unroll
            for (int mt = 0; mt < 2; mt++) {
                const int row = wm * 32 + mt * 16 + lrow_a;
                const uint32_t addr = aTile + row * 128 +
                    (((uint32_t)((kk * 2 + ahalf) ^ lxor)) << 4);
                ldsm_x4(a[mt][0], a[mt][1], a[mt][2], a[mt][3], addr);
            }
#pragma unroll
            for (int bt = 0; bt < 4; bt++) {
                const int row = wn * 64 + bt * 16 + lrow_b;
                const uint32_t addr = bTile + row * 128 +
                    (((uint32_t)((kk * 2 + bhalf) ^ lxor)) << 4);
                uint32_t r0, r1, r2, r3;
                ldsm_x4(r0, r1, r2, r3, addr);
                b[2 * bt][0] = r0;     b[2 * bt][1] = r1;
                b[2 * bt + 1][0] = r2; b[2 * bt + 1][1] = r3;
            }
#pragma unroll
            for (int mt = 0; mt < 2; mt++)
#pragma unroll
                for (int nt = 0; nt < 8; nt++)
                    mma16816(c[mt][nt], a[mt], b[nt]);
        }
        __syncthreads();
    }

    const int g  = lane >> 2;
    const int tg = lane & 3;
#pragma unroll
    for (int mt = 0; mt < 2; mt++) {
        const int m0 = mBase + wm * 32 + mt * 16 + g;
#pragma unroll
        for (int nt = 0; nt < 8; nt++) {
            const int n0 = nBase + wn * 64 + nt * 8 + tg * 2;
#pragma unroll
            for (int half = 0; half < 2; half++) {
                const int m = m0 + half * 8;
                const float v0 = c[mt][nt][half * 2 + 0];
                const float v1 = c[mt][nt][half * 2 + 1];
                if (MODE == 0) {
                    store_hi(outSplit, M, m, n0,     fmaxf(v0 + aux[n0],     0.0f));
                    store_hi(outSplit, M, m, n0 + 1, fmaxf(v1 + aux[n0 + 1], 0.0f));
                } else {
                    float2 r = make_float2(v0 + aux[n0], v1 + aux[n0 + 1]);
                    *(float2*)(outF + (size_t)m * N + n0) = r;
                }
            }
        }
    }
}

// ===================== persistent fused recurrence ===========================
#define GATE_W 68
#define NCTAS 128
__device__ __forceinline__ float sigf(float x) { return 1.0f / (1.0f + __expf(-x)); }

__global__ __launch_bounds__(256, 1)
void rec_persist_k(__half* __restrict__ hc0, __half* __restrict__ hc1,
                   const __half* __restrict__ whh, const float* __restrict__ xg,
                   const float* __restrict__ W_out, const float* __restrict__ c0,
                   float* __restrict__ out, float* __restrict__ hT, float* __restrict__ cT)
{
    extern __shared__ char smraw[];
    const uint32_t sbase = smem_u32(smraw);   // [2 bufs][A 16KB | B 8KB] = 48KB
    float* gate_sm = (float*)smraw;

    const int tid  = threadIdx.x;
    const int lane = tid & 31;
    const int wid  = tid >> 5;
    const int wm   = wid & 3;
    const int wn   = wid >> 2;
    const int nBase = blockIdx.x * 64;
    const int mBase = blockIdx.y * 128;
    const int NIT = 16;

    const int lrow_a = ((lane >> 3) & 1) * 8 + (lane & 7);
    const int lrow_b = (lane >> 4) * 8 + (lane & 7);
    const int lxor   = lane & 7;
    const int ahalf  = lane >> 4;
    const int bhalf  = (lane >> 3) & 1;

    const int bloc = tid >> 1;
    const int b = mBase + bloc;
    const int jh = (tid & 1) * 8;
    const int j0 = (nBase >> 2) + jh;
    float cc[8], wout[8];
#pragma unroll
    for (int jj = 0; jj < 8; jj++) {
        cc[jj]   = c0[b * HH + j0 + jj];
        wout[jj] = W_out[j0 + jj];
    }

    volatile int* barp = &g_bar;

    for (int t = 0; t < TT; t++) {
        const __half* hcR = (t & 1) ? hc1 : hc0;
        __half*       hcW = (t & 1) ? hc0 : hc1;
        const float*  xg_t = xg + (size_t)t * BB * GG;

        float4 xr[8];
        const float4* xp = (const float4*)(xg_t + (size_t)b * GG + nBase) + jh;
#pragma unroll
        for (int jj = 0; jj < 8; jj++) xr[jj] = xp[jj];

        float c[2][4][4];
#pragma unroll
        for (int i = 0; i < 2; i++)
#pragma unroll
            for (int j = 0; j < 4; j++)
#pragma unroll
                for (int k = 0; k < 4; k++) c[i][j][k] = 0.0f;

        LOAD_CHUNK(hcR, whh, 256, 4096, mBase, nBase, 128, 64, 0, 0, sbase);
        cp_commit();

        for (int i = 0; i < NIT; i++) {
            const int buf = i & 1;
            if (i + 1 < NIT) {
                LOAD_CHUNK(hcR, whh, 256, 4096, mBase, nBase, 128, 64, i + 1, i + 1,
                           sbase + ((i + 1) & 1) * 24576u);
                cp_commit();
                cp_wait<1>();
            } else {
                cp_wait<0>();
            }
            __syncthreads();

            const uint32_t aTile = sbase + buf * 24576u;
            const uint32_t bTile = aTile + 16384u;
#pragma unroll
            for (int kk = 0; kk < 4; kk++) {
                uint32_t a[2][4], bfrag[4][2];
#pragma unroll
                for (int mt = 0; mt < 2; mt++) {
                    const int row = wm * 32 + mt * 16 + lrow_a;
                    const uint32_t addr = aTile + row * 128 +
                        (((uint32_t)((kk * 2 + ahalf) ^ lxor)) << 4);
                    ldsm_x4(a[mt][0], a[mt][1], a[mt][2], a[mt][3], addr);
                }
#pragma unroll
                for (int bt = 0; bt < 2; bt++) {
                    const int row = wn * 32 + bt * 16 + lrow_b;
                    const uint32_t addr = bTile + row * 128 +
                        (((uint32_t)((kk * 2 + bhalf) ^ lxor)) << 4);
                    uint32_t r0, r1, r2, r3;
                    ldsm_x4(r0, r1, r2, r3, addr);
                    bfrag[2 * bt][0] = r0;     bfrag[2 * bt][1] = r1;
                    bfrag[2 * bt + 1][0] = r2; bfrag[2 * bt + 1][1] = r3;
                }
#pragma unroll
                for (int mt = 0; mt < 2; mt++)
#pragma unroll
                    for (int nt = 0; nt < 4; nt++)
                        mma16816(c[mt][nt], a[mt], bfrag[nt]);
            }
            __syncthreads();
        }

        const int g  = lane >> 2;
        const int tg = lane & 3;
#pragma unroll
        for (int mt = 0; mt < 2; mt++) {
#pragma unroll
            for (int nt = 0; nt < 4; nt++) {
                const int col = wn * 32 + nt * 8 + tg * 2;
#pragma unroll
                for (int half = 0; half < 2; half++) {
                    const int row = wm * 32 + mt * 16 + g + half * 8;
                    gate_sm[row * GATE_W + col]     = c[mt][nt][half * 2 + 0];
                    gate_sm[row * GATE_W + col + 1] = c[mt][nt][half * 2 + 1];
                }
            }
        }
        __syncthreads();

        float osum = 0.0f;
#pragma unroll
        for (int jj = 0; jj < 8; jj++) {
            const int jloc = jh + jj;
            const int j = (nBase >> 2) + jloc;
            const float4 mm = *(const float4*)&gate_sm[bloc * GATE_W + jloc * 4];
            const float ig = sigf(mm.x + xr[jj].x);
            const float fg = sigf(mm.y + xr[jj].y);
            const float gg = tanhf(mm.z + xr[jj].z);
            const float og = sigf(mm.w + xr[jj].w);
            cc[jj] = fg * cc[jj] + ig * gg;
            const float h = og * tanhf(cc[jj]);

            const int chunk = j >> 6, col = j & 63;
            hcW[((size_t)chunk * BB + b) * 64 + col] = __float2half_rn(h);
            osum += h * wout[jj];
            if (t == TT - 1) { hT[b * HH + j] = h; cT[b * HH + j] = cc[jj]; }
        }
        atomicAdd(&out[t * BB + b], osum);

        __threadfence();
        __syncthreads();
        if (tid == 0) {
            atomicAdd(&g_bar, 1);
            const int target = NCTAS * (t + 1);
            while (*barp < target) { __nanosleep(64); }
        }
        __syncthreads();
        __threadfence();
    }
}

// ===================== conversion / pointwise kernels ========================
__global__ void split_hi_k(const float* __restrict__ src, __half* __restrict__ dst,
                           int R, int K)
{
    const size_t i = (size_t)blockIdx.x * blockDim.x + threadIdx.x;
    const int r = (int)(i / K);
    const int k = (int)(i - (size_t)r * K);
    const int chunk = k >> 6, col = k & 63;
    dst[((size_t)chunk * R + r) * 64 + col] = __float2half_rn(src[i]);
}

// gate-permuted, hi-only: dest row r' = j*4+g  (W_ih and W_hh)
__global__ void split_perm_hi_k(const float* __restrict__ src, __half* __restrict__ dst)
{
    const size_t i = (size_t)blockIdx.x * blockDim.x + threadIdx.x;
    const int r = (int)(i >> 10);
    const int k = (int)(i & 1023);
    const int gt = r >> 10, j = r & 1023;
    const int rp = j * 4 + gt;
    const int chunk = k >> 6, col = k & 63;
    dst[((size_t)chunk * 4096 + rp) * 64 + col] = __float2half_rn(src[i]);
}

// merged setup: bias combine + h0 convert + out init + barrier reset
__global__ void setup_k(const float* __restrict__ b_ih, const float* __restrict__ b_hh,
                        const float* __restrict__ h0,
                        float* __restrict__ out, const float* __restrict__ b_out)
{
    const int i = blockIdx.x * blockDim.x + threadIdx.x;  // [0, B*H)
    if (i == 0) g_bar = 0;
    if (i < GG) {
        const int gt = i & 3, j = i >> 2;
        const int s = gt * HH + j;
        g_bias[i] = b_ih[s] + b_hh[s];
    }
    if (i < TT * BB) out[i] = b_out[0];
    const int b = i >> 10, j = i & 1023;
    const int chunk = j >> 6, col = j & 63;
    g_hc[((size_t)chunk * BB + b) * 64 + col] = __float2half_rn(h0[i]);
}

// ===================== launch ================================================
#define SMEM_BIG 65536
#define SMEM_REC 49152

extern "C" void kernel_launch(void* const* d_in, const int* in_sizes, int n_in,
                              void* d_out, int out_size)
{
    const float* inputs = (const float*)d_in[0];
    const float* h0     = (const float*)d_in[1];
    const float* c0     = (const float*)d_in[2];
    const float* W1     = (const float*)d_in[3];
    const float* b1     = (const float*)d_in[4];
    const float* W_ih   = (const float*)d_in[5];
    const float* W_hh   = (const float*)d_in[6];
    const float* b_ih   = (const float*)d_in[7];
    const float* b_hh   = (const float*)d_in[8];
    const float* W_out  = (const float*)d_in[9];
    const float* b_out  = (const float*)d_in[10];

    float* out = (float*)d_out;
    float* hT  = out + TT * BB;
    float* cT  = hT + BB * HH;

    __half *pinc, *pxc, *pw1c, *pwihc, *pwhhc, *phc;
    float *pxg, *pbias;
    cudaGetSymbolAddress((void**)&pinc,  g_inc);
    cudaGetSymbolAddress((void**)&pxc,   g_xc);
    cudaGetSymbolAddress((void**)&pw1c,  g_w1c);
    cudaGetSymbolAddress((void**)&pwihc, g_wihc);
    cudaGetSymbolAddress((void**)&pwhhc, g_whhc);
    cudaGetSymbolAddress((void**)&phc,   g_hc);
    cudaGetSymbolAddress((void**)&pxg,   g_xg);
    cudaGetSymbolAddress((void**)&pbias, g_bias);

    cudaFuncSetAttribute((const void*)gemm_mma<0>, cudaFuncAttributeMaxDynamicSharedMemorySize, SMEM_BIG);
    cudaFuncSetAttribute((const void*)gemm_mma<1>, cudaFuncAttributeMaxDynamicSharedMemorySize, SMEM_BIG);
    cudaFuncSetAttribute((const void*)rec_persist_k, cudaFuncAttributeMaxDynamicSharedMemorySize, SMEM_REC);

    // conversions (all hi-only now)
    split_hi_k<<<(32768 * 512) / 256, 256>>>(inputs, pinc, 32768, 512);
    split_hi_k<<<(1024 * 512) / 256, 256>>>(W1, pw1c, 1024, 512);
    split_perm_hi_k<<<(4096 * 1024) / 256, 256>>>(W_ih, pwihc);
    split_perm_hi_k<<<(4096 * 1024) / 256, 256>>>(W_hh, pwhhc);
    setup_k<<<(BB * HH) / 256, 256>>>(b_ih, b_hh, h0, out, b_out);

    // GEMM1: x = relu(inputs @ W1^T + b1) -> hi store g_xc  (1-pass, C=8)
    {
        dim3 grid(HH / 128, 32768 / 128);
        gemm_mma<0><<<grid, 256, SMEM_BIG>>>(pinc, pw1c, b1, nullptr, pxc, 32768, HH, 8);
    }
    // GEMM2: xg' = x_hi @ W_ih_hi'^T + bias' -> g_xg  (1-pass, C=16)
    {
        dim3 grid(GG / 128, 32768 / 128);
        gemm_mma<1><<<grid, 256, SMEM_BIG>>>(pxc, pwihc, pbias, pxg, nullptr, 32768, GG, 16);
    }
    // persistent recurrence: single launch, 128 co-resident CTAs
    {
        dim3 grid(GG / 64, BB / 128);
        rec_persist_k<<<grid, 256, SMEM_REC>>>(phc, phc + HSPLIT, pwhhc, pxg,
                                               W_out, c0, out, hT, cT);
    }
}